// round 13
// baseline (speedup 1.0000x reference)
#include <cuda_runtime.h>
#include <cuda_fp16.h>
#include <cstdint>

#define Bn 8
#define Cc 512
#define CQ 64
#define Hh 128
#define Ww 128
#define HW (Hh*Ww)   // 16384

// ---------------------------------------------------------------------------
// Device scratch
// ---------------------------------------------------------------------------
__device__ __half g_v16[(size_t)Bn*Cc*HW];                // [b][c][s] fp16 single
__device__ __half g_w_hi[640*Cc];
__device__ __half g_w_lo[640*Cc];
__device__ float g_bias[640];

// ---------------------------------------------------------------------------
// helpers
// ---------------------------------------------------------------------------
__device__ __forceinline__ uint32_t smem_u32(const void* p) {
    uint32_t a;
    asm("{ .reg .u64 t; cvta.to.shared.u64 t, %1; cvt.u32.u64 %0, t; }" : "=r"(a) : "l"(p));
    return a;
}
__device__ __forceinline__ void cp16(uint32_t dst, const void* src) {
    asm volatile("cp.async.cg.shared.global [%0], [%1], 16;" :: "r"(dst), "l"(src));
}
#define CP_COMMIT()      asm volatile("cp.async.commit_group;" ::: "memory")
#define CP_WAIT_GROUP(n) asm volatile("cp.async.wait_group %0;" :: "n"(n) : "memory")

__device__ __forceinline__ void mma_f16(float c[4], uint32_t a0, uint32_t a1, uint32_t a2, uint32_t a3,
                                        uint32_t b0, uint32_t b1) {
    asm volatile("mma.sync.aligned.m16n8k16.row.col.f32.f16.f16.f32 "
                 "{%0,%1,%2,%3}, {%4,%5,%6,%7}, {%8,%9}, {%0,%1,%2,%3};"
                 : "+f"(c[0]), "+f"(c[1]), "+f"(c[2]), "+f"(c[3])
                 : "r"(a0), "r"(a1), "r"(a2), "r"(a3), "r"(b0), "r"(b1));
}
__device__ __forceinline__ void ldsm4(uint32_t& r0, uint32_t& r1, uint32_t& r2, uint32_t& r3,
                                      uint32_t addr) {
    asm volatile("ldmatrix.sync.aligned.m8n8.x4.shared.b16 {%0,%1,%2,%3}, [%4];"
                 : "=r"(r0), "=r"(r1), "=r"(r2), "=r"(r3) : "r"(addr));
}
__device__ __forceinline__ uint32_t prmt(uint32_t a, uint32_t b, uint32_t s) {
    uint32_t d;
    asm("prmt.b32 %0, %1, %2, %3;" : "=r"(d) : "r"(a), "r"(b), "r"(s));
    return d;
}
__device__ __forceinline__ uint32_t pack_hilo(float v) {
    __half h = __float2half_rn(v);
    float r = v - __half2float(h);
    __half l = __float2half_rn(r);
    return (uint32_t)__half_as_ushort(h) | ((uint32_t)__half_as_ushort(l) << 16);
}
__device__ __forceinline__ uint32_t pack2h(float a, float b) {
    __half ha = __float2half_rn(a), hb = __float2half_rn(b);
    return (uint32_t)__half_as_ushort(ha) | ((uint32_t)__half_as_ushort(hb) << 16);
}

// ---------------------------------------------------------------------------
// Prep: W -> fp16 hi/lo (concat rows), bias concat
// ---------------------------------------------------------------------------
__global__ void prep_w(const float* __restrict__ Wq, const float* __restrict__ bq,
                       const float* __restrict__ Wk, const float* __restrict__ bk,
                       const float* __restrict__ Wv, const float* __restrict__ bv)
{
    int r = blockIdx.x;
    const float* src; float bias;
    if (r < 64)       { src = Wq + (size_t)r*Cc;        bias = bq[r]; }
    else if (r < 128) { src = Wk + (size_t)(r-64)*Cc;   bias = bk[r-64]; }
    else              { src = Wv + (size_t)(r-128)*Cc;  bias = bv[r-128]; }
    if (threadIdx.x == 0) g_bias[r] = bias;
    for (int c = threadIdx.x; c < Cc; c += blockDim.x) {
        float v = src[c];
        __half h = __float2half_rn(v);
        g_w_hi[(size_t)r*Cc + c] = h;
        g_w_lo[(size_t)r*Cc + c] = __float2half_rn(v - __half2float(h));
    }
}

// ---------------------------------------------------------------------------
// V GEMM: rows 128..639 of W, 1-term fp16. K chunks of 32, 256 threads,
// 2 CTAs/SM. B (x) loaded fp32 raw + converted/transposed in-kernel.
// stage layout: Ah(128x80B) | Bh(128x80B), 3 stages; raw fp32 2 x 16KB.
// ---------------------------------------------------------------------------
#define V_SEG  10240
#define V_STAGE (2*V_SEG)      // 20480
#define V_RAW  61440           // after 3 stages
#define SM_V   94208           // 61440 + 2*16384

__device__ __forceinline__ void load_w_v(uint32_t sb, int tid, int k0, int m0)
{
    #pragma unroll
    for (int i = tid; i < 512; i += 256) {
        int r = i >> 2, u = i & 3;
        cp16(sb + r*80 + u*16, g_w_hi + (size_t)(128 + m0 + r)*Cc + k0 + u*8);
    }
}
__device__ __forceinline__ void load_x_v(uint32_t rawp, int tid, int k0,
                                         const float* x, int b, int n0)
{
    #pragma unroll
    for (int i = tid; i < 1024; i += 256) {
        int ch = i >> 5, u = i & 31;
        cp16(rawp + ch*512 + u*16, x + ((size_t)b*Cc + k0 + ch)*HW + n0 + u*4);
    }
}

__global__ void __launch_bounds__(256, 2) qkv_gemm_v(const float* __restrict__ x)
{
    extern __shared__ char smem[];
    const uint32_t sbase = smem_u32(smem);
    const int tid = threadIdx.x, wid = tid >> 5, lane = tid & 31;
    const int g = lane >> 2, q = lane & 3;
    const int m0 = blockIdx.x * 128;
    const int n0 = blockIdx.y * 128;
    const int b  = blockIdx.z;
    const int wm = wid & 1, wn = wid >> 1;
    const int lmat = lane >> 3, lrow = lane & 7;

    float acc[4][4][4];
    #pragma unroll
    for (int i = 0; i < 4; i++)
        #pragma unroll
        for (int j = 0; j < 4; j++)
            #pragma unroll
            for (int e = 0; e < 4; e++) acc[i][j][e] = 0.f;

    load_w_v(sbase, tid, 0, m0);              load_x_v(sbase + V_RAW, tid, 0, x, b, n0);           CP_COMMIT();
    load_w_v(sbase + V_STAGE, tid, 32, m0);   load_x_v(sbase + V_RAW + 16384, tid, 32, x, b, n0);  CP_COMMIT();

    for (int c = 0; c < 16; c++) {
        if (c < 15) { CP_WAIT_GROUP(1); } else { CP_WAIT_GROUP(0); }
        __syncthreads();

        const uint32_t st = sbase + (c % 3)*V_STAGE;
        // convert raw fp32 [ch][s] -> Bh[s][ch] fp16 (transpose)
        {
            const float* rawf = (const float*)(smem + V_RAW + (c & 1)*16384);
            int s = tid & 127, grp = tid >> 7;   // grp 0..1, 8 ch-pairs each
            #pragma unroll
            for (int p = 0; p < 8; p++) {
                int chp = grp*8 + p;
                float a  = rawf[(2*chp    )*128 + s];
                float c2 = rawf[(2*chp + 1)*128 + s];
                *(uint32_t*)(smem + (st - sbase) + V_SEG + s*80 + chp*4) = pack2h(a, c2);
            }
        }
        __syncthreads();   // raw[c&1] free; stage(c+2)%3 free (read finished iter c-1)

        if (c + 2 < 16) {
            load_w_v(sbase + ((c+2) % 3)*V_STAGE, tid, (c+2)*32, m0);
            load_x_v(sbase + V_RAW + (c & 1)*16384, tid, (c+2)*32, x, b, n0);
            CP_COMMIT();
        }

        #pragma unroll
        for (int ks = 0; ks < 2; ks++) {
            uint32_t ah[4][4], bh[4][2];
            #pragma unroll
            for (int tm = 0; tm < 4; tm++) {
                uint32_t ra = st + (wm*64 + tm*16 + (lmat&1)*8 + lrow)*80 + ks*32 + (lmat>>1)*16;
                ldsm4(ah[tm][0], ah[tm][1], ah[tm][2], ah[tm][3], ra);
            }
            #pragma unroll
            for (int tp = 0; tp < 2; tp++) {
                uint32_t rb = st + V_SEG + (wn*32 + (tp*2 + (lmat>>1))*8 + lrow)*80 + ks*32 + (lmat&1)*16;
                ldsm4(bh[tp*2][0], bh[tp*2][1], bh[tp*2+1][0], bh[tp*2+1][1], rb);
            }
            #pragma unroll
            for (int tm = 0; tm < 4; tm++)
                #pragma unroll
                for (int tn = 0; tn < 4; tn++)
                    mma_f16(acc[tm][tn], ah[tm][0], ah[tm][1], ah[tm][2], ah[tm][3], bh[tn][0], bh[tn][1]);
        }
    }

    #pragma unroll
    for (int tm = 0; tm < 4; tm++) {
        int cv = m0 + wm*64 + tm*16 + g;
        float bias0 = g_bias[128 + cv];
        float bias1 = g_bias[128 + cv + 8];
        #pragma unroll
        for (int tn = 0; tn < 4; tn++) {
            int n = n0 + wn*32 + tn*8 + q*2;
            uint32_t pa = pack2h(acc[tm][tn][0] + bias0, acc[tm][tn][1] + bias0);
            uint32_t pb = pack2h(acc[tm][tn][2] + bias1, acc[tm][tn][3] + bias1);
            *(uint32_t*)&g_v16[((size_t)b*Cc + cv)*HW + n]     = pa;
            *(uint32_t*)&g_v16[((size_t)b*Cc + cv + 8)*HW + n] = pb;
        }
    }
}

// ---------------------------------------------------------------------------
// Fused QK-GEMM + attention kernel. One CTA per (b,h), 512 threads.
// Phase 0 loads x fp32 raw and converts to fp16 hi/lo in-kernel.
// smem: [0,122880) stages Ah|Al|Bh|Bl x3 (sq/sk overlay at 0..69632)
//       [122880,155648) raw fp32 x2  -> E/ST overlay here after phase 0
//       [190464,225280) v double buffer (2 x 64ch)
// ---------------------------------------------------------------------------
#define ROWB 80
#define SEG  10240
#define STAGE_QK (4*SEG)       // 40960
#define AOFF_RAW 122880

#define AQK_ROWB 272
#define AA_ROWB  272
#define AV_ROWB  272
#define AE_STRIDE 132
#define AST_STRIDE 132
#define AOFF_Q   0
#define AOFF_K   34816
#define AOFF_A   0
#define AOFF_E   122880        // overlays raw (dead after phase 0)
#define AOFF_ST  122880
#define AOFF_V   190464
#define AV_BUFB  17408         // 64 rows * 272
#define ATT_SMEM 225280

__device__ __forceinline__ void load_w_qk(uint32_t sb, int tid, int k0)
{
    const __half* srcs[2] = { g_w_hi + k0, g_w_lo + k0 };
    #pragma unroll
    for (int i = tid; i < 1024; i += 512) {
        int seg = i >> 9;
        int r = (i & 511) >> 2, u = i & 3;
        cp16(sb + seg*SEG + r*ROWB + u*16, srcs[seg] + (size_t)r*Cc + u*8);
    }
}
__device__ __forceinline__ void load_x_qk(uint32_t rawp, int tid, int k0,
                                          const float* x, int b, int h)
{
    #pragma unroll
    for (int i = tid; i < 1024; i += 512) {
        int ch = i >> 5, u = i & 31;
        cp16(rawp + ch*512 + u*16, x + ((size_t)b*Cc + k0 + ch)*HW + h*128 + u*4);
    }
}
__device__ __forceinline__ void att_load_v(uint32_t sbv, int tid, int b, int h, int cc)
{
    const __half* src0 = g_v16 + (((size_t)b*Cc + cc)*Hh + h)*Ww;
    #pragma unroll
    for (int i = tid; i < 1024; i += 512) {
        int r = i >> 4, u = i & 15;
        cp16(sbv + r*AV_ROWB + u*16, src0 + (size_t)r*HW + u*8);
    }
    CP_COMMIT();
}

__global__ void __launch_bounds__(512, 1) attn_kernel(
    const float* __restrict__ x,
    const float* __restrict__ gamma_p,
    float* __restrict__ outp)
{
    extern __shared__ char smem[];
    const uint32_t sbase = smem_u32(smem);
    const int tid = threadIdx.x, wid = tid >> 5, lane = tid & 31;
    const int g = lane >> 2, q = lane & 3;
    const int bh = blockIdx.x;
    const int b = bh >> 7, h = bh & 127;
    const float gma = gamma_p[0];
    const int lmat = lane >> 3, lrow = lane & 7;

    // v prefetch — chunks 0,1 (oldest groups; drain naturally)
    att_load_v(sbase + AOFF_V, tid, b, h, 0);
    att_load_v(sbase + AOFF_V + AV_BUFB, tid, b, h, 64);

    // ======================= Phase 0: QK GEMM ==============================
    {
        const int wm = wid & 3, wn = wid >> 2;   // warp tile 32m x 32n
        float acc[2][4][4];
        #pragma unroll
        for (int i = 0; i < 2; i++)
            #pragma unroll
            for (int j = 0; j < 4; j++)
                #pragma unroll
                for (int e = 0; e < 4; e++) acc[i][j][e] = 0.f;

        load_w_qk(sbase, tid, 0);              load_x_qk(sbase + AOFF_RAW, tid, 0, x, b, h);           CP_COMMIT();
        load_w_qk(sbase + STAGE_QK, tid, 32);  load_x_qk(sbase + AOFF_RAW + 16384, tid, 32, x, b, h);  CP_COMMIT();

        for (int c = 0; c < 16; c++) {
            if (c < 15) { CP_WAIT_GROUP(1); } else { CP_WAIT_GROUP(0); }
            __syncthreads();

            const uint32_t sb = sbase + (c % 3)*STAGE_QK;
            // convert raw fp32 [ch][s] -> Bh[s][ch], Bl[s][ch]
            {
                const float* rawf = (const float*)(smem + AOFF_RAW + (c & 1)*16384);
                uint32_t boff = (sb - sbase) + 2*SEG;
                int s = tid & 127, grp = tid >> 7;   // grp 0..3, 4 ch-pairs each
                #pragma unroll
                for (int p = 0; p < 4; p++) {
                    int chp = grp*4 + p;
                    float a  = rawf[(2*chp    )*128 + s];
                    float c2 = rawf[(2*chp + 1)*128 + s];
                    __half ah2 = __float2half_rn(a),  ch2 = __float2half_rn(c2);
                    __half al2 = __float2half_rn(a - __half2float(ah2));
                    __half cl2 = __float2half_rn(c2 - __half2float(ch2));
                    uint32_t hi = (uint32_t)__half_as_ushort(ah2) | ((uint32_t)__half_as_ushort(ch2) << 16);
                    uint32_t lo = (uint32_t)__half_as_ushort(al2) | ((uint32_t)__half_as_ushort(cl2) << 16);
                    *(uint32_t*)(smem + boff + s*80 + chp*4)       = hi;
                    *(uint32_t*)(smem + boff + SEG + s*80 + chp*4) = lo;
                }
            }
            __syncthreads();   // raw[c&1] + stage(c+2)%3 free

            if (c + 2 < 16) {
                load_w_qk(sbase + ((c+2) % 3)*STAGE_QK, tid, (c+2)*32);
                load_x_qk(sbase + AOFF_RAW + (c & 1)*16384, tid, (c+2)*32, x, b, h);
                CP_COMMIT();
            }

            #pragma unroll
            for (int ks = 0; ks < 2; ks++) {
                uint32_t ah[2][4], al[2][4], bhf[4][2], blf[4][2];
                #pragma unroll
                for (int tm = 0; tm < 2; tm++) {
                    uint32_t ra = sb + (wm*32 + tm*16 + (lmat&1)*8 + lrow)*ROWB + ks*32 + (lmat>>1)*16;
                    ldsm4(ah[tm][0], ah[tm][1], ah[tm][2], ah[tm][3], ra);
                    ldsm4(al[tm][0], al[tm][1], al[tm][2], al[tm][3], ra + SEG);
                }
                #pragma unroll
                for (int tp = 0; tp < 2; tp++) {
                    uint32_t rb = sb + 2*SEG + (wn*32 + (tp*2 + (lmat>>1))*8 + lrow)*ROWB + ks*32 + (lmat&1)*16;
                    ldsm4(bhf[tp*2][0], bhf[tp*2][1], bhf[tp*2+1][0], bhf[tp*2+1][1], rb);
                    ldsm4(blf[tp*2][0], blf[tp*2][1], blf[tp*2+1][0], blf[tp*2+1][1], rb + SEG);
                }
                #pragma unroll
                for (int tm = 0; tm < 2; tm++)
                    #pragma unroll
                    for (int tn = 0; tn < 4; tn++) {
                        mma_f16(acc[tm][tn], ah[tm][0], ah[tm][1], ah[tm][2], ah[tm][3], bhf[tn][0], bhf[tn][1]);
                        mma_f16(acc[tm][tn], ah[tm][0], ah[tm][1], ah[tm][2], ah[tm][3], blf[tn][0], blf[tn][1]);
                        mma_f16(acc[tm][tn], al[tm][0], al[tm][1], al[tm][2], al[tm][3], bhf[tn][0], bhf[tn][1]);
                    }
            }
        }
        // all warps must finish reading stage 0 (= sq/sk overlay) first
        __syncthreads();

        // Epilogue: bias, pack (hi,lo) into smem sq/sk (overlays stages).
        #pragma unroll
        for (int tm = 0; tm < 2; tm++) {
            int mrow = wm*32 + tm*16 + g;
            float bias0 = g_bias[mrow];
            float bias1 = g_bias[mrow + 8];
            #pragma unroll
            for (int tn = 0; tn < 4; tn++) {
                int w = wn*32 + tn*8 + q*2;  // even
                uint32_t p0 = pack_hilo(acc[tm][tn][0] + bias0);
                uint32_t p1 = pack_hilo(acc[tm][tn][1] + bias0);
                uint32_t p2 = pack_hilo(acc[tm][tn][2] + bias1);
                uint32_t p3 = pack_hilo(acc[tm][tn][3] + bias1);
                #pragma unroll
                for (int rr = 0; rr < 2; rr++) {
                    int oc = mrow + rr*8;
                    uint32_t pa = rr ? p2 : p0;
                    uint32_t pb = rr ? p3 : p1;
                    if (oc < 64) {
                        int i = oc*2 + (w >> 6), cc = w & 63;
                        *(uint2*)(smem + AOFF_Q + i*AQK_ROWB + cc*4) = make_uint2(pa, pb);
                    } else {
                        int cq = oc - 64, cc = w >> 1;
                        *(uint32_t*)(smem + AOFF_K + cq*AQK_ROWB + cc*4)        = pa;
                        *(uint32_t*)(smem + AOFF_K + (64 + cq)*AQK_ROWB + cc*4) = pb;
                    }
                }
            }
        }
    }
    __syncthreads();

    const int wi = wid & 3;    // i 32-tile
    const int wj = wid >> 2;   // m 32-col / c 16-col group

    // ======================= Phase 1: energy (3-term) ======================
    {
        float e[2][4][4];
        #pragma unroll
        for (int a1 = 0; a1 < 2; a1++)
            #pragma unroll
            for (int a2 = 0; a2 < 4; a2++)
                #pragma unroll
                for (int a3 = 0; a3 < 4; a3++) e[a1][a2][a3] = 0.f;

        #pragma unroll
        for (int ks = 0; ks < 4; ks++) {
            uint32_t ah[2][4], al[2][4], bh_[4][2], bl_[4][2];
            #pragma unroll
            for (int ti = 0; ti < 2; ti++) {
                uint32_t ra = AOFF_Q + (wi*32 + ti*16 + g)*AQK_ROWB + ks*64 + q*8;
                uint2 w00 = *(const uint2*)(smem + ra);
                uint2 w10 = *(const uint2*)(smem + ra + 8*AQK_ROWB);
                uint2 w01 = *(const uint2*)(smem + ra + 32);
                uint2 w11 = *(const uint2*)(smem + ra + 8*AQK_ROWB + 32);
                ah[ti][0] = prmt(w00.x, w00.y, 0x5410); al[ti][0] = prmt(w00.x, w00.y, 0x7632);
                ah[ti][1] = prmt(w10.x, w10.y, 0x5410); al[ti][1] = prmt(w10.x, w10.y, 0x7632);
                ah[ti][2] = prmt(w01.x, w01.y, 0x5410); al[ti][2] = prmt(w01.x, w01.y, 0x7632);
                ah[ti][3] = prmt(w11.x, w11.y, 0x5410); al[ti][3] = prmt(w11.x, w11.y, 0x7632);
            }
            #pragma unroll
            for (int tn = 0; tn < 4; tn++) {
                uint32_t rb = AOFF_K + (wj*32 + tn*8 + g)*AQK_ROWB + ks*64 + q*8;
                uint2 u0 = *(const uint2*)(smem + rb);
                uint2 u1 = *(const uint2*)(smem + rb + 32);
                bh_[tn][0] = prmt(u0.x, u0.y, 0x5410); bl_[tn][0] = prmt(u0.x, u0.y, 0x7632);
                bh_[tn][1] = prmt(u1.x, u1.y, 0x5410); bl_[tn][1] = prmt(u1.x, u1.y, 0x7632);
            }
            #pragma unroll
            for (int ti = 0; ti < 2; ti++)
                #pragma unroll
                for (int tn = 0; tn < 4; tn++) {
                    mma_f16(e[ti][tn], ah[ti][0], ah[ti][1], ah[ti][2], ah[ti][3], bh_[tn][0], bh_[tn][1]);
                    mma_f16(e[ti][tn], al[ti][0], al[ti][1], al[ti][2], al[ti][3], bh_[tn][0], bh_[tn][1]);
                    mma_f16(e[ti][tn], ah[ti][0], ah[ti][1], ah[ti][2], ah[ti][3], bl_[tn][0], bl_[tn][1]);
                }
        }
        float* Ef = (float*)(smem + AOFF_E);
        #pragma unroll
        for (int ti = 0; ti < 2; ti++)
            #pragma unroll
            for (int tn = 0; tn < 4; tn++) {
                int ri = wi*32 + ti*16 + g, cj = wj*32 + tn*8 + 2*q;
                *(float2*)&Ef[ri*AE_STRIDE + cj]     = make_float2(e[ti][tn][0], e[ti][tn][1]);
                *(float2*)&Ef[(ri+8)*AE_STRIDE + cj] = make_float2(e[ti][tn][2], e[ti][tn][3]);
            }
    }
    __syncthreads();

    // ======================= Phase 2: softmax + pack A =====================
    {
        float* Ef = (float*)(smem + AOFF_E);
        int i = tid >> 2, qt = tid & 3;
        float* row = Ef + i*AE_STRIDE + qt*32;
        float mx = -1e30f;
        #pragma unroll 8
        for (int j = 0; j < 32; j++) mx = fmaxf(mx, row[j]);
        mx = fmaxf(mx, __shfl_xor_sync(0xFFFFFFFFu, mx, 1));
        mx = fmaxf(mx, __shfl_xor_sync(0xFFFFFFFFu, mx, 2));
        float s = 0.f;
        #pragma unroll 8
        for (int j = 0; j < 32; j++) { float p = __expf(row[j] - mx); row[j] = p; s += p; }
        s += __shfl_xor_sync(0xFFFFFFFFu, s, 1);
        s += __shfl_xor_sync(0xFFFFFFFFu, s, 2);
        float inv = 1.f / s;
        uint32_t* arow = (uint32_t*)(smem + AOFF_A + i*AA_ROWB + qt*64);
        #pragma unroll 8
        for (int j = 0; j < 32; j += 2)
            arow[j >> 1] = pack2h(row[j]*inv, row[j+1]*inv);
    }
    __syncthreads();

    // ======================= Phase 3: out = A @ V (8 chunks of 64 ch) ======
    float* STf = (float*)(smem + AOFF_ST);
    for (int ci = 0; ci < 8; ci++) {
        if (ci < 7) { CP_WAIT_GROUP(1); } else { CP_WAIT_GROUP(0); }
        __syncthreads();   // vb[ci&1] ready; STf free

        const uint32_t vb = AOFF_V + (ci & 1)*AV_BUFB;
        float o[2][2][4];
        #pragma unroll
        for (int a1 = 0; a1 < 2; a1++)
            #pragma unroll
            for (int a2 = 0; a2 < 2; a2++)
                #pragma unroll
                for (int a3 = 0; a3 < 4; a3++) o[a1][a2][a3] = 0.f;

        #pragma unroll
        for (int ks = 0; ks < 8; ks++) {
            uint32_t a0[2], a1r[2], a2[2], a3[2], b0[2], b1[2];
            #pragma unroll
            for (int ti = 0; ti < 2; ti++) {
                uint32_t ra = AOFF_A + (wi*32 + ti*16 + g)*AA_ROWB + ks*32 + q*4;
                a0[ti]  = *(const uint32_t*)(smem + ra);
                a1r[ti] = *(const uint32_t*)(smem + ra + 8*AA_ROWB);
                a2[ti]  = *(const uint32_t*)(smem + ra + 16);
                a3[ti]  = *(const uint32_t*)(smem + ra + 8*AA_ROWB + 16);
            }
            #pragma unroll
            for (int tn = 0; tn < 2; tn++) {
                uint32_t rb = vb + (wj*16 + tn*8 + g)*AV_ROWB + ks*32 + q*4;
                b0[tn] = *(const uint32_t*)(smem + rb);
                b1[tn] = *(const uint32_t*)(smem + rb + 16);
            }
            #pragma unroll
            for (int ti = 0; ti < 2; ti++)
                #pragma unroll
                for (int tn = 0; tn < 2; tn++)
                    mma_f16(o[ti][tn], a0[ti], a1r[ti], a2[ti], a3[ti], b0[tn], b1[tn]);
        }

        // stage out[i][c'] -> ST[c'][i]
        #pragma unroll
        for (int ti = 0; ti < 2; ti++)
            #pragma unroll
            for (int tn = 0; tn < 2; tn++) {
                int ri = wi*32 + ti*16 + g, cj = wj*16 + tn*8 + 2*q;
                STf[cj*AST_STRIDE + ri]          = o[ti][tn][0];
                STf[(cj+1)*AST_STRIDE + ri]      = o[ti][tn][1];
                STf[cj*AST_STRIDE + ri + 8]      = o[ti][tn][2];
                STf[(cj+1)*AST_STRIDE + ri + 8]  = o[ti][tn][3];
            }
        __syncthreads();   // all vb reads + ST writes complete

        if (ci + 2 < 8) att_load_v(sbase + vb, tid, b, h, (ci+2)*64);

        // coalesced writeback: out[b][c][h][i] = gma*o + x
        #pragma unroll
        for (int rr = 0; rr < 4; rr++) {
            int r = wid*4 + rr;
            int c = ci*64 + r;
            size_t gofs = (((size_t)b*Cc + c)*Hh + h)*Ww + lane*4;
            float4 xr = *(const float4*)(x + gofs);
            float4 ov = *(const float4*)(STf + r*AST_STRIDE + lane*4);
            *(float4*)(outp + gofs) = make_float4(gma*ov.x + xr.x, gma*ov.y + xr.y,
                                                  gma*ov.z + xr.z, gma*ov.w + xr.w);
        }
    }
}

// ---------------------------------------------------------------------------
extern "C" void kernel_launch(void* const* d_in, const int* in_sizes, int n_in,
                              void* d_out, int out_size)
{
    (void)in_sizes; (void)n_in; (void)out_size;
    const float* x     = (const float*)d_in[0];
    const float* Wq    = (const float*)d_in[1];
    const float* bq    = (const float*)d_in[2];
    const float* Wk    = (const float*)d_in[3];
    const float* bk    = (const float*)d_in[4];
    const float* Wv    = (const float*)d_in[5];
    const float* bv    = (const float*)d_in[6];
    const float* gamma = (const float*)d_in[7];
    float* out = (float*)d_out;

    prep_w<<<640, 128>>>(Wq, bq, Wk, bk, Wv, bv);

    cudaFuncSetAttribute(qkv_gemm_v, cudaFuncAttributeMaxDynamicSharedMemorySize, SM_V);
    qkv_gemm_v<<<dim3(4, 128, Bn), 256, SM_V>>>(x);

    cudaFuncSetAttribute(attn_kernel, cudaFuncAttributeMaxDynamicSharedMemorySize, ATT_SMEM);
    attn_kernel<<<Bn*Hh, 512, ATT_SMEM>>>(x, gamma, out);
}

// round 14
// speedup vs baseline: 1.0387x; 1.0387x over previous
#include <cuda_runtime.h>
#include <cuda_fp16.h>
#include <cstdint>

#define Bn 8
#define Cc 512
#define CQ 64
#define Hh 128
#define Ww 128
#define HW (Hh*Ww)   // 16384

// ---------------------------------------------------------------------------
// Device scratch
// ---------------------------------------------------------------------------
__device__ __half g_v16[(size_t)Bn*Cc*HW];                // [b][c][s] fp16 single
__device__ __half g_xt_hi[(size_t)Bn*HW*Cc];              // xT[b][s][ch]
__device__ __half g_xt_lo[(size_t)Bn*HW*Cc];
__device__ __half g_w_hi[640*Cc];
__device__ __half g_w_lo[640*Cc];
__device__ float g_bias[640];

// ---------------------------------------------------------------------------
// helpers
// ---------------------------------------------------------------------------
__device__ __forceinline__ uint32_t smem_u32(const void* p) {
    uint32_t a;
    asm("{ .reg .u64 t; cvta.to.shared.u64 t, %1; cvt.u32.u64 %0, t; }" : "=r"(a) : "l"(p));
    return a;
}
__device__ __forceinline__ void cp16(uint32_t dst, const void* src) {
    asm volatile("cp.async.cg.shared.global [%0], [%1], 16;" :: "r"(dst), "l"(src));
}
#define CP_COMMIT()      asm volatile("cp.async.commit_group;" ::: "memory")
#define CP_WAIT_GROUP(n) asm volatile("cp.async.wait_group %0;" :: "n"(n) : "memory")

__device__ __forceinline__ void mma_f16(float c[4], uint32_t a0, uint32_t a1, uint32_t a2, uint32_t a3,
                                        uint32_t b0, uint32_t b1) {
    asm volatile("mma.sync.aligned.m16n8k16.row.col.f32.f16.f16.f32 "
                 "{%0,%1,%2,%3}, {%4,%5,%6,%7}, {%8,%9}, {%0,%1,%2,%3};"
                 : "+f"(c[0]), "+f"(c[1]), "+f"(c[2]), "+f"(c[3])
                 : "r"(a0), "r"(a1), "r"(a2), "r"(a3), "r"(b0), "r"(b1));
}
__device__ __forceinline__ void ldsm4(uint32_t& r0, uint32_t& r1, uint32_t& r2, uint32_t& r3,
                                      uint32_t addr) {
    asm volatile("ldmatrix.sync.aligned.m8n8.x4.shared.b16 {%0,%1,%2,%3}, [%4];"
                 : "=r"(r0), "=r"(r1), "=r"(r2), "=r"(r3) : "r"(addr));
}
__device__ __forceinline__ uint32_t prmt(uint32_t a, uint32_t b, uint32_t s) {
    uint32_t d;
    asm("prmt.b32 %0, %1, %2, %3;" : "=r"(d) : "r"(a), "r"(b), "r"(s));
    return d;
}
__device__ __forceinline__ uint32_t pack_hilo(float v) {
    __half h = __float2half_rn(v);
    float r = v - __half2float(h);
    __half l = __float2half_rn(r);
    return (uint32_t)__half_as_ushort(h) | ((uint32_t)__half_as_ushort(l) << 16);
}
__device__ __forceinline__ uint32_t pack2h(float a, float b) {
    __half ha = __float2half_rn(a), hb = __float2half_rn(b);
    return (uint32_t)__half_as_ushort(ha) | ((uint32_t)__half_as_ushort(hb) << 16);
}

// ---------------------------------------------------------------------------
// Prep: x[b][ch][s] -> xT hi/lo [b][s][ch]; 214 blocks also convert W (3 rows
// each) and bias, folding the old prep_w kernel into this launch.
// ---------------------------------------------------------------------------
__global__ void __launch_bounds__(256) prep_all(
    const float* __restrict__ x,
    const float* __restrict__ Wq, const float* __restrict__ bq,
    const float* __restrict__ Wk, const float* __restrict__ bk,
    const float* __restrict__ Wv, const float* __restrict__ bv)
{
    __shared__ float st[64*65];
    const int b = blockIdx.z, ch0 = blockIdx.y * 64, s0 = blockIdx.x * 64;

    // --- folded W conversion (was prep_w) ---
    if (b == 0 && blockIdx.y == 0 && blockIdx.x < 214) {
        #pragma unroll
        for (int rr = 0; rr < 3; rr++) {
            int r = blockIdx.x * 3 + rr;
            if (r < 640) {
                const float* src; float bias;
                if (r < 64)       { src = Wq + (size_t)r*Cc;        bias = bq[r]; }
                else if (r < 128) { src = Wk + (size_t)(r-64)*Cc;   bias = bk[r-64]; }
                else              { src = Wv + (size_t)(r-128)*Cc;  bias = bv[r-128]; }
                if (threadIdx.x == 0) g_bias[r] = bias;
                for (int c = threadIdx.x; c < Cc; c += 256) {
                    float v = src[c];
                    __half h = __float2half_rn(v);
                    g_w_hi[(size_t)r*Cc + c] = h;
                    g_w_lo[(size_t)r*Cc + c] = __float2half_rn(v - __half2float(h));
                }
            }
        }
    }

    // --- x transpose + hi/lo convert ---
    const float* xb = x + ((size_t)b*Cc + ch0)*HW + s0;
    for (int i = threadIdx.x; i < 64*64; i += 256) {
        int ch = i >> 6, s = i & 63;
        st[ch*65 + s] = xb[(size_t)ch*HW + s];
    }
    __syncthreads();
    for (int u = threadIdx.x; u < 512; u += 256) {
        int s = u >> 3, c8 = (u & 7) * 8;
        uint32_t hi[4], lo[4];
        #pragma unroll
        for (int j = 0; j < 4; j++) {
            float a = st[(c8 + 2*j    )*65 + s];
            float c = st[(c8 + 2*j + 1)*65 + s];
            __half ah = __float2half_rn(a), ch_ = __float2half_rn(c);
            __half al = __float2half_rn(a - __half2float(ah));
            __half cl = __float2half_rn(c - __half2float(ch_));
            hi[j] = (uint32_t)__half_as_ushort(ah) | ((uint32_t)__half_as_ushort(ch_) << 16);
            lo[j] = (uint32_t)__half_as_ushort(al) | ((uint32_t)__half_as_ushort(cl) << 16);
        }
        size_t off = ((size_t)(b*HW + s0 + s))*Cc + ch0 + c8;
        *(uint4*)(g_xt_hi + off) = make_uint4(hi[0], hi[1], hi[2], hi[3]);
        *(uint4*)(g_xt_lo + off) = make_uint4(lo[0], lo[1], lo[2], lo[3]);
    }
}

// ---------------------------------------------------------------------------
// V GEMM: rows 128..639 of W, 1-term fp16 (hi only). K chunks of 64,
// 256 threads, 2 CTAs/SM, ldmatrix loads, single-barrier pipeline. (R12)
// ---------------------------------------------------------------------------
#define V_ROWB 144
#define V_SEG  18432
#define STAGE_V (2*V_SEG)
#define SM_V (3*STAGE_V)       // 110592

__device__ __forceinline__ void load_chunk_v(uint32_t sb, int tid, int k0, int m0, size_t bofs)
{
    const __half* srcs[2] = {
        g_w_hi + (size_t)(128 + m0)*Cc + k0,
        g_xt_hi + bofs + k0 };
    #pragma unroll
    for (int i = tid; i < 2048; i += 256) {
        int seg = i >> 10;
        int r = (i & 1023) >> 3, u = i & 7;
        cp16(sb + seg*V_SEG + r*V_ROWB + u*16, srcs[seg] + (size_t)r*Cc + u*8);
    }
    CP_COMMIT();
}

__global__ void __launch_bounds__(256, 2) qkv_gemm_v()
{
    extern __shared__ char smem[];
    const uint32_t sbase = smem_u32(smem);
    const int tid = threadIdx.x, wid = tid >> 5, lane = tid & 31;
    const int g = lane >> 2, q = lane & 3;
    const int m0 = blockIdx.x * 128;
    const int n0 = blockIdx.y * 128;
    const int b  = blockIdx.z;
    const size_t bofs = ((size_t)b*HW + n0)*Cc;
    const int wm = wid & 1, wn = wid >> 1;
    const int lmat = lane >> 3, lrow = lane & 7;

    float acc[4][4][4];
    #pragma unroll
    for (int i = 0; i < 4; i++)
        #pragma unroll
        for (int j = 0; j < 4; j++)
            #pragma unroll
            for (int e = 0; e < 4; e++) acc[i][j][e] = 0.f;

    load_chunk_v(sbase, tid, 0, m0, bofs);
    load_chunk_v(sbase + STAGE_V, tid, 64, m0, bofs);

    for (int c = 0; c < 8; c++) {
        if (c < 7) { CP_WAIT_GROUP(1); } else { CP_WAIT_GROUP(0); }
        __syncthreads();
        if (c + 2 < 8)
            load_chunk_v(sbase + ((c+2) % 3)*STAGE_V, tid, (c+2)*64, m0, bofs);

        const uint32_t sb = sbase + (c % 3)*STAGE_V;
        #pragma unroll
        for (int ks = 0; ks < 4; ks++) {
            uint32_t ah[4][4], bh[4][2];
            #pragma unroll
            for (int tm = 0; tm < 4; tm++) {
                uint32_t ra = sb + (wm*64 + tm*16 + (lmat&1)*8 + lrow)*V_ROWB + ks*32 + (lmat>>1)*16;
                ldsm4(ah[tm][0], ah[tm][1], ah[tm][2], ah[tm][3], ra);
            }
            #pragma unroll
            for (int tp = 0; tp < 2; tp++) {
                uint32_t rb = sb + V_SEG + (wn*32 + (tp*2 + (lmat>>1))*8 + lrow)*V_ROWB + ks*32 + (lmat&1)*16;
                ldsm4(bh[tp*2][0], bh[tp*2][1], bh[tp*2+1][0], bh[tp*2+1][1], rb);
            }
            #pragma unroll
            for (int tm = 0; tm < 4; tm++)
                #pragma unroll
                for (int tn = 0; tn < 4; tn++)
                    mma_f16(acc[tm][tn], ah[tm][0], ah[tm][1], ah[tm][2], ah[tm][3], bh[tn][0], bh[tn][1]);
        }
    }

    #pragma unroll
    for (int tm = 0; tm < 4; tm++) {
        int cv = m0 + wm*64 + tm*16 + g;
        float bias0 = g_bias[128 + cv];
        float bias1 = g_bias[128 + cv + 8];
        #pragma unroll
        for (int tn = 0; tn < 4; tn++) {
            int n = n0 + wn*32 + tn*8 + q*2;
            uint32_t pa = pack2h(acc[tm][tn][0] + bias0, acc[tm][tn][1] + bias0);
            uint32_t pb = pack2h(acc[tm][tn][2] + bias1, acc[tm][tn][3] + bias1);
            *(uint32_t*)&g_v16[((size_t)b*Cc + cv)*HW + n]     = pa;
            *(uint32_t*)&g_v16[((size_t)b*Cc + cv + 8)*HW + n] = pb;
        }
    }
}

// ---------------------------------------------------------------------------
// Fused QK-GEMM + attention kernel. One CTA per (b,h), 512 threads. (R12)
// ---------------------------------------------------------------------------
#define ROWB 80
#define SEG  10240
#define STAGE_QK (4*SEG)       // 40960

#define AQK_ROWB 272
#define AA_ROWB  272
#define AV_ROWB  272
#define AE_STRIDE 132
#define AST_STRIDE 132
#define AOFF_Q   0
#define AOFF_K   34816
#define AOFF_A   0
#define AOFF_E   69632
#define AOFF_ST  69632
#define AOFF_V   137216
#define AV_BUFB  34816         // 128 rows * 272
#define ATT_SMEM 206848

__device__ __forceinline__ void load_chunk_qk(uint32_t sb, int tid, int k0, size_t bofs)
{
    const __half* srcs[4] = {
        g_w_hi + k0, g_w_lo + k0,
        g_xt_hi + bofs + k0, g_xt_lo + bofs + k0 };
    #pragma unroll
    for (int i = tid; i < 2048; i += 512) {
        int seg = i >> 9;
        int r = (i & 511) >> 2, u = i & 3;
        cp16(sb + seg*SEG + r*ROWB + u*16, srcs[seg] + (size_t)r*Cc + u*8);
    }
    CP_COMMIT();
}

__device__ __forceinline__ void att_load_v(uint32_t sbv, int tid, int b, int h, int cc)
{
    const __half* src0 = g_v16 + (((size_t)b*Cc + cc)*Hh + h)*Ww;
    #pragma unroll
    for (int i = tid; i < 2048; i += 512) {
        int r = i >> 4, u = i & 15;
        cp16(sbv + r*AV_ROWB + u*16, src0 + (size_t)r*HW + u*8);
    }
    CP_COMMIT();
}

__global__ void __launch_bounds__(512, 1) attn_kernel(
    const float* __restrict__ x,
    const float* __restrict__ gamma_p,
    float* __restrict__ outp)
{
    extern __shared__ char smem[];
    const uint32_t sbase = smem_u32(smem);
    const int tid = threadIdx.x, wid = tid >> 5, lane = tid & 31;
    const int g = lane >> 2, q = lane & 3;
    const int bh = blockIdx.x;
    const int b = bh >> 7, h = bh & 127;
    const float gma = gamma_p[0];
    const size_t bofs = ((size_t)b*HW + h*128)*Cc;
    const int lmat = lane >> 3, lrow = lane & 7;

    // v prefetch (outside stage region) — chunks 0,1
    att_load_v(sbase + AOFF_V, tid, b, h, 0);
    att_load_v(sbase + AOFF_V + AV_BUFB, tid, b, h, 128);

    // ======================= Phase 0: QK GEMM ==============================
    {
        const int wm = wid & 3, wn = wid >> 2;   // warp tile 32m x 32n
        float acc[2][4][4];
        #pragma unroll
        for (int i = 0; i < 2; i++)
            #pragma unroll
            for (int j = 0; j < 4; j++)
                #pragma unroll
                for (int e = 0; e < 4; e++) acc[i][j][e] = 0.f;

        load_chunk_qk(sbase, tid, 0, bofs);
        load_chunk_qk(sbase + STAGE_QK, tid, 32, bofs);

        for (int c = 0; c < 16; c++) {
            if (c < 15) { CP_WAIT_GROUP(1); } else { CP_WAIT_GROUP(0); }
            __syncthreads();
            if (c + 2 < 16)
                load_chunk_qk(sbase + ((c+2) % 3)*STAGE_QK, tid, (c+2)*32, bofs);

            const uint32_t sb = sbase + (c % 3)*STAGE_QK;
            #pragma unroll
            for (int ks = 0; ks < 2; ks++) {
                uint32_t ah[2][4], al[2][4], bhf[4][2], blf[4][2];
                #pragma unroll
                for (int tm = 0; tm < 2; tm++) {
                    uint32_t ra = sb + (wm*32 + tm*16 + (lmat&1)*8 + lrow)*ROWB + ks*32 + (lmat>>1)*16;
                    ldsm4(ah[tm][0], ah[tm][1], ah[tm][2], ah[tm][3], ra);
                    ldsm4(al[tm][0], al[tm][1], al[tm][2], al[tm][3], ra + SEG);
                }
                #pragma unroll
                for (int tp = 0; tp < 2; tp++) {
                    uint32_t rb = sb + 2*SEG + (wn*32 + (tp*2 + (lmat>>1))*8 + lrow)*ROWB + ks*32 + (lmat&1)*16;
                    ldsm4(bhf[tp*2][0], bhf[tp*2][1], bhf[tp*2+1][0], bhf[tp*2+1][1], rb);
                    ldsm4(blf[tp*2][0], blf[tp*2][1], blf[tp*2+1][0], blf[tp*2+1][1], rb + SEG);
                }
                #pragma unroll
                for (int tm = 0; tm < 2; tm++)
                    #pragma unroll
                    for (int tn = 0; tn < 4; tn++) {
                        mma_f16(acc[tm][tn], ah[tm][0], ah[tm][1], ah[tm][2], ah[tm][3], bhf[tn][0], bhf[tn][1]);
                        mma_f16(acc[tm][tn], ah[tm][0], ah[tm][1], ah[tm][2], ah[tm][3], blf[tn][0], blf[tn][1]);
                        mma_f16(acc[tm][tn], al[tm][0], al[tm][1], al[tm][2], al[tm][3], bhf[tn][0], bhf[tn][1]);
                    }
            }
        }
        __syncthreads();   // all stage-0 reads done before sq/sk overlay

        // Epilogue: bias, pack (hi,lo) into smem sq/sk (overlays stages).
        #pragma unroll
        for (int tm = 0; tm < 2; tm++) {
            int mrow = wm*32 + tm*16 + g;
            float bias0 = g_bias[mrow];
            float bias1 = g_bias[mrow + 8];
            #pragma unroll
            for (int tn = 0; tn < 4; tn++) {
                int w = wn*32 + tn*8 + q*2;  // even
                uint32_t p0 = pack_hilo(acc[tm][tn][0] + bias0);
                uint32_t p1 = pack_hilo(acc[tm][tn][1] + bias0);
                uint32_t p2 = pack_hilo(acc[tm][tn][2] + bias1);
                uint32_t p3 = pack_hilo(acc[tm][tn][3] + bias1);
                #pragma unroll
                for (int rr = 0; rr < 2; rr++) {
                    int oc = mrow + rr*8;
                    uint32_t pa = rr ? p2 : p0;
                    uint32_t pb = rr ? p3 : p1;
                    if (oc < 64) {
                        int i = oc*2 + (w >> 6), cc = w & 63;
                        *(uint2*)(smem + AOFF_Q + i*AQK_ROWB + cc*4) = make_uint2(pa, pb);
                    } else {
                        int cq = oc - 64, cc = w >> 1;
                        *(uint32_t*)(smem + AOFF_K + cq*AQK_ROWB + cc*4)        = pa;
                        *(uint32_t*)(smem + AOFF_K + (64 + cq)*AQK_ROWB + cc*4) = pb;
                    }
                }
            }
        }
    }
    __syncthreads();

    const int wi = wid & 3;    // i 32-tile
    const int wj = wid >> 2;   // m/c 32-col group

    // ======================= Phase 1: energy (3-term) ======================
    {
        float e[2][4][4];
        #pragma unroll
        for (int a1 = 0; a1 < 2; a1++)
            #pragma unroll
            for (int a2 = 0; a2 < 4; a2++)
                #pragma unroll
                for (int a3 = 0; a3 < 4; a3++) e[a1][a2][a3] = 0.f;

        #pragma unroll
        for (int ks = 0; ks < 4; ks++) {
            uint32_t ah[2][4], al[2][4], bh_[4][2], bl_[4][2];
            #pragma unroll
            for (int ti = 0; ti < 2; ti++) {
                uint32_t ra = AOFF_Q + (wi*32 + ti*16 + g)*AQK_ROWB + ks*64 + q*8;
                uint2 w00 = *(const uint2*)(smem + ra);
                uint2 w10 = *(const uint2*)(smem + ra + 8*AQK_ROWB);
                uint2 w01 = *(const uint2*)(smem + ra + 32);
                uint2 w11 = *(const uint2*)(smem + ra + 8*AQK_ROWB + 32);
                ah[ti][0] = prmt(w00.x, w00.y, 0x5410); al[ti][0] = prmt(w00.x, w00.y, 0x7632);
                ah[ti][1] = prmt(w10.x, w10.y, 0x5410); al[ti][1] = prmt(w10.x, w10.y, 0x7632);
                ah[ti][2] = prmt(w01.x, w01.y, 0x5410); al[ti][2] = prmt(w01.x, w01.y, 0x7632);
                ah[ti][3] = prmt(w11.x, w11.y, 0x5410); al[ti][3] = prmt(w11.x, w11.y, 0x7632);
            }
            #pragma unroll
            for (int tn = 0; tn < 4; tn++) {
                uint32_t rb = AOFF_K + (wj*32 + tn*8 + g)*AQK_ROWB + ks*64 + q*8;
                uint2 u0 = *(const uint2*)(smem + rb);
                uint2 u1 = *(const uint2*)(smem + rb + 32);
                bh_[tn][0] = prmt(u0.x, u0.y, 0x5410); bl_[tn][0] = prmt(u0.x, u0.y, 0x7632);
                bh_[tn][1] = prmt(u1.x, u1.y, 0x5410); bl_[tn][1] = prmt(u1.x, u1.y, 0x7632);
            }
            #pragma unroll
            for (int ti = 0; ti < 2; ti++)
                #pragma unroll
                for (int tn = 0; tn < 4; tn++) {
                    mma_f16(e[ti][tn], ah[ti][0], ah[ti][1], ah[ti][2], ah[ti][3], bh_[tn][0], bh_[tn][1]);
                    mma_f16(e[ti][tn], al[ti][0], al[ti][1], al[ti][2], al[ti][3], bh_[tn][0], bh_[tn][1]);
                    mma_f16(e[ti][tn], ah[ti][0], ah[ti][1], ah[ti][2], ah[ti][3], bl_[tn][0], bl_[tn][1]);
                }
        }
        float* Ef = (float*)(smem + AOFF_E);
        #pragma unroll
        for (int ti = 0; ti < 2; ti++)
            #pragma unroll
            for (int tn = 0; tn < 4; tn++) {
                int ri = wi*32 + ti*16 + g, cj = wj*32 + tn*8 + 2*q;
                *(float2*)&Ef[ri*AE_STRIDE + cj]     = make_float2(e[ti][tn][0], e[ti][tn][1]);
                *(float2*)&Ef[(ri+8)*AE_STRIDE + cj] = make_float2(e[ti][tn][2], e[ti][tn][3]);
            }
    }
    __syncthreads();

    // ======================= Phase 2: softmax + pack A =====================
    {
        float* Ef = (float*)(smem + AOFF_E);
        int i = tid >> 2, qt = tid & 3;
        float* row = Ef + i*AE_STRIDE + qt*32;
        float mx = -1e30f;
        #pragma unroll 8
        for (int j = 0; j < 32; j++) mx = fmaxf(mx, row[j]);
        mx = fmaxf(mx, __shfl_xor_sync(0xFFFFFFFFu, mx, 1));
        mx = fmaxf(mx, __shfl_xor_sync(0xFFFFFFFFu, mx, 2));
        float s = 0.f;
        #pragma unroll 8
        for (int j = 0; j < 32; j++) { float p = __expf(row[j] - mx); row[j] = p; s += p; }
        s += __shfl_xor_sync(0xFFFFFFFFu, s, 1);
        s += __shfl_xor_sync(0xFFFFFFFFu, s, 2);
        float inv = 1.f / s;
        uint32_t* arow = (uint32_t*)(smem + AOFF_A + i*AA_ROWB + qt*64);
        #pragma unroll 8
        for (int j = 0; j < 32; j += 2)
            arow[j >> 1] = pack2h(row[j]*inv, row[j+1]*inv);
    }
    __syncthreads();

    // ======================= Phase 3: out = A @ V ==========================
    float* STf = (float*)(smem + AOFF_ST);
    for (int ci = 0; ci < 4; ci++) {
        if (ci < 3) { CP_WAIT_GROUP(1); } else { CP_WAIT_GROUP(0); }
        __syncthreads();   // vb[ci&1] ready; STf free

        const uint32_t vb = AOFF_V + (ci & 1)*AV_BUFB;
        float o[2][4][4];
        #pragma unroll
        for (int a1 = 0; a1 < 2; a1++)
            #pragma unroll
            for (int a2 = 0; a2 < 4; a2++)
                #pragma unroll
                for (int a3 = 0; a3 < 4; a3++) o[a1][a2][a3] = 0.f;

        #pragma unroll
        for (int ks = 0; ks < 8; ks++) {
            uint32_t a0[2], a1r[2], a2[2], a3[2], b0[4], b1[4];
            #pragma unroll
            for (int ti = 0; ti < 2; ti++) {
                uint32_t ra = AOFF_A + (wi*32 + ti*16 + g)*AA_ROWB + ks*32 + q*4;
                a0[ti]  = *(const uint32_t*)(smem + ra);
                a1r[ti] = *(const uint32_t*)(smem + ra + 8*AA_ROWB);
                a2[ti]  = *(const uint32_t*)(smem + ra + 16);
                a3[ti]  = *(const uint32_t*)(smem + ra + 8*AA_ROWB + 16);
            }
            #pragma unroll
            for (int tn = 0; tn < 4; tn++) {
                uint32_t rb = vb + (wj*32 + tn*8 + g)*AV_ROWB + ks*32 + q*4;
                b0[tn] = *(const uint32_t*)(smem + rb);
                b1[tn] = *(const uint32_t*)(smem + rb + 16);
            }
            #pragma unroll
            for (int ti = 0; ti < 2; ti++)
                #pragma unroll
                for (int tn = 0; tn < 4; tn++)
                    mma_f16(o[ti][tn], a0[ti], a1r[ti], a2[ti], a3[ti], b0[tn], b1[tn]);
        }

        // stage out[i][c'] -> ST[c'][i]
        #pragma unroll
        for (int ti = 0; ti < 2; ti++)
            #pragma unroll
            for (int tn = 0; tn < 4; tn++) {
                int ri = wi*32 + ti*16 + g, cj = wj*32 + tn*8 + 2*q;
                STf[cj*AST_STRIDE + ri]          = o[ti][tn][0];
                STf[(cj+1)*AST_STRIDE + ri]      = o[ti][tn][1];
                STf[cj*AST_STRIDE + ri + 8]      = o[ti][tn][2];
                STf[(cj+1)*AST_STRIDE + ri + 8]  = o[ti][tn][3];
            }
        __syncthreads();   // all vb reads + ST writes complete

        if (ci + 2 < 4) att_load_v(sbase + vb, tid, b, h, (ci+2)*128);

        // coalesced writeback: out[b][c][h][i] = gma*o + x
        #pragma unroll
        for (int rr = 0; rr < 8; rr++) {
            int r = wid*8 + rr;
            int c = ci*128 + r;
            size_t gofs = (((size_t)b*Cc + c)*Hh + h)*Ww + lane*4;
            float4 xr = *(const float4*)(x + gofs);
            float4 ov = *(const float4*)(STf + r*AST_STRIDE + lane*4);
            *(float4*)(outp + gofs) = make_float4(gma*ov.x + xr.x, gma*ov.y + xr.y,
                                                  gma*ov.z + xr.z, gma*ov.w + xr.w);
        }
    }
}

// ---------------------------------------------------------------------------
extern "C" void kernel_launch(void* const* d_in, const int* in_sizes, int n_in,
                              void* d_out, int out_size)
{
    (void)in_sizes; (void)n_in; (void)out_size;
    const float* x     = (const float*)d_in[0];
    const float* Wq    = (const float*)d_in[1];
    const float* bq    = (const float*)d_in[2];
    const float* Wk    = (const float*)d_in[3];
    const float* bk    = (const float*)d_in[4];
    const float* Wv    = (const float*)d_in[5];
    const float* bv    = (const float*)d_in[6];
    const float* gamma = (const float*)d_in[7];
    float* out = (float*)d_out;

    dim3 gx(HW/64, Cc/64, Bn);
    prep_all<<<gx, 256>>>(x, Wq, bq, Wk, bk, Wv, bv);

    cudaFuncSetAttribute(qkv_gemm_v, cudaFuncAttributeMaxDynamicSharedMemorySize, SM_V);
    qkv_gemm_v<<<dim3(4, 128, Bn), 256, SM_V>>>();

    cudaFuncSetAttribute(attn_kernel, cudaFuncAttributeMaxDynamicSharedMemorySize, ATT_SMEM);
    attn_kernel<<<Bn*Hh, 512, ATT_SMEM>>>(x, gamma, out);
}

// round 15
// speedup vs baseline: 1.1610x; 1.1178x over previous
#include <cuda_runtime.h>
#include <cuda_fp16.h>
#include <cstdint>

#define Bn 8
#define Cc 512
#define CQ 64
#define Hh 128
#define Ww 128
#define HW (Hh*Ww)   // 16384

// ---------------------------------------------------------------------------
// Device scratch
// ---------------------------------------------------------------------------
__device__ __half g_v16[(size_t)Bn*Cc*HW];                // [b][c][s] fp16 single
__device__ __half g_xt_hi[(size_t)Bn*HW*Cc];              // xT[b][s][ch] fp16 single
__device__ __half g_w_hi[640*Cc];
__device__ __half g_w_lo[640*Cc];
__device__ float g_bias[640];

// ---------------------------------------------------------------------------
// helpers
// ---------------------------------------------------------------------------
__device__ __forceinline__ uint32_t smem_u32(const void* p) {
    uint32_t a;
    asm("{ .reg .u64 t; cvta.to.shared.u64 t, %1; cvt.u32.u64 %0, t; }" : "=r"(a) : "l"(p));
    return a;
}
__device__ __forceinline__ void cp16(uint32_t dst, const void* src) {
    asm volatile("cp.async.cg.shared.global [%0], [%1], 16;" :: "r"(dst), "l"(src));
}
#define CP_COMMIT()      asm volatile("cp.async.commit_group;" ::: "memory")
#define CP_WAIT_GROUP(n) asm volatile("cp.async.wait_group %0;" :: "n"(n) : "memory")

__device__ __forceinline__ void mma_f16(float c[4], uint32_t a0, uint32_t a1, uint32_t a2, uint32_t a3,
                                        uint32_t b0, uint32_t b1) {
    asm volatile("mma.sync.aligned.m16n8k16.row.col.f32.f16.f16.f32 "
                 "{%0,%1,%2,%3}, {%4,%5,%6,%7}, {%8,%9}, {%0,%1,%2,%3};"
                 : "+f"(c[0]), "+f"(c[1]), "+f"(c[2]), "+f"(c[3])
                 : "r"(a0), "r"(a1), "r"(a2), "r"(a3), "r"(b0), "r"(b1));
}
__device__ __forceinline__ void ldsm4(uint32_t& r0, uint32_t& r1, uint32_t& r2, uint32_t& r3,
                                      uint32_t addr) {
    asm volatile("ldmatrix.sync.aligned.m8n8.x4.shared.b16 {%0,%1,%2,%3}, [%4];"
                 : "=r"(r0), "=r"(r1), "=r"(r2), "=r"(r3) : "r"(addr));
}
__device__ __forceinline__ uint32_t prmt(uint32_t a, uint32_t b, uint32_t s) {
    uint32_t d;
    asm("prmt.b32 %0, %1, %2, %3;" : "=r"(d) : "r"(a), "r"(b), "r"(s));
    return d;
}
__device__ __forceinline__ uint32_t pack_hilo(float v) {
    __half h = __float2half_rn(v);
    float r = v - __half2float(h);
    __half l = __float2half_rn(r);
    return (uint32_t)__half_as_ushort(h) | ((uint32_t)__half_as_ushort(l) << 16);
}
__device__ __forceinline__ uint32_t pack2h(float a, float b) {
    __half ha = __float2half_rn(a), hb = __float2half_rn(b);
    return (uint32_t)__half_as_ushort(ha) | ((uint32_t)__half_as_ushort(hb) << 16);
}

// ---------------------------------------------------------------------------
// Prep: x[b][ch][s] -> xT fp16 [b][s][ch] (single); 214 blocks also convert
// W hi/lo (3 rows each) and bias.
// ---------------------------------------------------------------------------
__global__ void __launch_bounds__(256) prep_all(
    const float* __restrict__ x,
    const float* __restrict__ Wq, const float* __restrict__ bq,
    const float* __restrict__ Wk, const float* __restrict__ bk,
    const float* __restrict__ Wv, const float* __restrict__ bv)
{
    __shared__ float st[64*65];
    const int b = blockIdx.z, ch0 = blockIdx.y * 64, s0 = blockIdx.x * 64;

    if (b == 0 && blockIdx.y == 0 && blockIdx.x < 214) {
        #pragma unroll
        for (int rr = 0; rr < 3; rr++) {
            int r = blockIdx.x * 3 + rr;
            if (r < 640) {
                const float* src; float bias;
                if (r < 64)       { src = Wq + (size_t)r*Cc;        bias = bq[r]; }
                else if (r < 128) { src = Wk + (size_t)(r-64)*Cc;   bias = bk[r-64]; }
                else              { src = Wv + (size_t)(r-128)*Cc;  bias = bv[r-128]; }
                if (threadIdx.x == 0) g_bias[r] = bias;
                for (int c = threadIdx.x; c < Cc; c += 256) {
                    float v = src[c];
                    __half h = __float2half_rn(v);
                    g_w_hi[(size_t)r*Cc + c] = h;
                    g_w_lo[(size_t)r*Cc + c] = __float2half_rn(v - __half2float(h));
                }
            }
        }
    }

    const float* xb = x + ((size_t)b*Cc + ch0)*HW + s0;
    for (int i = threadIdx.x; i < 64*64; i += 256) {
        int ch = i >> 6, s = i & 63;
        st[ch*65 + s] = xb[(size_t)ch*HW + s];
    }
    __syncthreads();
    for (int u = threadIdx.x; u < 512; u += 256) {
        int s = u >> 3, c8 = (u & 7) * 8;
        uint32_t hi[4];
        #pragma unroll
        for (int j = 0; j < 4; j++) {
            float a = st[(c8 + 2*j    )*65 + s];
            float c = st[(c8 + 2*j + 1)*65 + s];
            hi[j] = pack2h(a, c);
        }
        size_t off = ((size_t)(b*HW + s0 + s))*Cc + ch0 + c8;
        *(uint4*)(g_xt_hi + off) = make_uint4(hi[0], hi[1], hi[2], hi[3]);
    }
}

// ---------------------------------------------------------------------------
// V GEMM: rows 128..639 of W, 1-term fp16 (hi only). K chunks of 64,
// 256 threads, 2 CTAs/SM, ldmatrix loads, single-barrier pipeline. (R12)
// ---------------------------------------------------------------------------
#define V_ROWB 144
#define V_SEG  18432
#define STAGE_V (2*V_SEG)
#define SM_V (3*STAGE_V)       // 110592

__device__ __forceinline__ void load_chunk_v(uint32_t sb, int tid, int k0, int m0, size_t bofs)
{
    const __half* srcs[2] = {
        g_w_hi + (size_t)(128 + m0)*Cc + k0,
        g_xt_hi + bofs + k0 };
    #pragma unroll
    for (int i = tid; i < 2048; i += 256) {
        int seg = i >> 10;
        int r = (i & 1023) >> 3, u = i & 7;
        cp16(sb + seg*V_SEG + r*V_ROWB + u*16, srcs[seg] + (size_t)r*Cc + u*8);
    }
    CP_COMMIT();
}

__global__ void __launch_bounds__(256, 2) qkv_gemm_v()
{
    extern __shared__ char smem[];
    const uint32_t sbase = smem_u32(smem);
    const int tid = threadIdx.x, wid = tid >> 5, lane = tid & 31;
    const int g = lane >> 2, q = lane & 3;
    const int m0 = blockIdx.x * 128;
    const int n0 = blockIdx.y * 128;
    const int b  = blockIdx.z;
    const size_t bofs = ((size_t)b*HW + n0)*Cc;
    const int wm = wid & 1, wn = wid >> 1;
    const int lmat = lane >> 3, lrow = lane & 7;

    float acc[4][4][4];
    #pragma unroll
    for (int i = 0; i < 4; i++)
        #pragma unroll
        for (int j = 0; j < 4; j++)
            #pragma unroll
            for (int e = 0; e < 4; e++) acc[i][j][e] = 0.f;

    load_chunk_v(sbase, tid, 0, m0, bofs);
    load_chunk_v(sbase + STAGE_V, tid, 64, m0, bofs);

    for (int c = 0; c < 8; c++) {
        if (c < 7) { CP_WAIT_GROUP(1); } else { CP_WAIT_GROUP(0); }
        __syncthreads();
        if (c + 2 < 8)
            load_chunk_v(sbase + ((c+2) % 3)*STAGE_V, tid, (c+2)*64, m0, bofs);

        const uint32_t sb = sbase + (c % 3)*STAGE_V;
        #pragma unroll
        for (int ks = 0; ks < 4; ks++) {
            uint32_t ah[4][4], bh[4][2];
            #pragma unroll
            for (int tm = 0; tm < 4; tm++) {
                uint32_t ra = sb + (wm*64 + tm*16 + (lmat&1)*8 + lrow)*V_ROWB + ks*32 + (lmat>>1)*16;
                ldsm4(ah[tm][0], ah[tm][1], ah[tm][2], ah[tm][3], ra);
            }
            #pragma unroll
            for (int tp = 0; tp < 2; tp++) {
                uint32_t rb = sb + V_SEG + (wn*32 + (tp*2 + (lmat>>1))*8 + lrow)*V_ROWB + ks*32 + (lmat&1)*16;
                ldsm4(bh[tp*2][0], bh[tp*2][1], bh[tp*2+1][0], bh[tp*2+1][1], rb);
            }
            #pragma unroll
            for (int tm = 0; tm < 4; tm++)
                #pragma unroll
                for (int tn = 0; tn < 4; tn++)
                    mma_f16(acc[tm][tn], ah[tm][0], ah[tm][1], ah[tm][2], ah[tm][3], bh[tn][0], bh[tn][1]);
        }
    }

    #pragma unroll
    for (int tm = 0; tm < 4; tm++) {
        int cv = m0 + wm*64 + tm*16 + g;
        float bias0 = g_bias[128 + cv];
        float bias1 = g_bias[128 + cv + 8];
        #pragma unroll
        for (int tn = 0; tn < 4; tn++) {
            int n = n0 + wn*32 + tn*8 + q*2;
            uint32_t pa = pack2h(acc[tm][tn][0] + bias0, acc[tm][tn][1] + bias0);
            uint32_t pb = pack2h(acc[tm][tn][2] + bias1, acc[tm][tn][3] + bias1);
            *(uint32_t*)&g_v16[((size_t)b*Cc + cv)*HW + n]     = pa;
            *(uint32_t*)&g_v16[((size_t)b*Cc + cv + 8)*HW + n] = pb;
        }
    }
}

// ---------------------------------------------------------------------------
// Fused QK-GEMM + attention. One CTA per (b,h), 512 threads.
// Phase 0: 2-term QK (W hi/lo, x fp16 single). Stage = Ah|Al|Bh (3 segs).
// ---------------------------------------------------------------------------
#define ROWB 80
#define SEG  10240
#define STAGE_QK (3*SEG)       // 30720

#define AQK_ROWB 272
#define AA_ROWB  272
#define AV_ROWB  272
#define AE_STRIDE 132
#define AST_STRIDE 132
#define AOFF_Q   0
#define AOFF_K   34816
#define AOFF_A   0
#define AOFF_E   92160         // past the 3 stages (92160)
#define AOFF_ST  92160
#define AOFF_V   161792
#define AV_BUFB  17408         // 64 rows * 272
#define ATT_SMEM 196608

__device__ __forceinline__ void load_chunk_qk(uint32_t sb, int tid, int k0, size_t bofs)
{
    const __half* srcs[3] = { g_w_hi + k0, g_w_lo + k0, g_xt_hi + bofs + k0 };
    #pragma unroll
    for (int i = tid; i < 1536; i += 512) {
        int seg = i / 512;
        int r = (i & 511) >> 2, u = i & 3;
        cp16(sb + seg*SEG + r*ROWB + u*16, srcs[seg] + (size_t)r*Cc + u*8);
    }
    CP_COMMIT();
}

__device__ __forceinline__ void att_load_v(uint32_t sbv, int tid, int b, int h, int cc)
{
    const __half* src0 = g_v16 + (((size_t)b*Cc + cc)*Hh + h)*Ww;
    #pragma unroll
    for (int i = tid; i < 1024; i += 512) {
        int r = i >> 4, u = i & 15;
        cp16(sbv + r*AV_ROWB + u*16, src0 + (size_t)r*HW + u*8);
    }
    CP_COMMIT();
}

__global__ void __launch_bounds__(512, 1) attn_kernel(
    const float* __restrict__ x,
    const float* __restrict__ gamma_p,
    float* __restrict__ outp)
{
    extern __shared__ char smem[];
    const uint32_t sbase = smem_u32(smem);
    const int tid = threadIdx.x, wid = tid >> 5, lane = tid & 31;
    const int g = lane >> 2, q = lane & 3;
    const int bh = blockIdx.x;
    const int b = bh >> 7, h = bh & 127;
    const float gma = gamma_p[0];
    const size_t bofs = ((size_t)b*HW + h*128)*Cc;
    const int lmat = lane >> 3, lrow = lane & 7;

    // v prefetch — chunks 0,1 (64 channels each)
    att_load_v(sbase + AOFF_V, tid, b, h, 0);
    att_load_v(sbase + AOFF_V + AV_BUFB, tid, b, h, 64);

    // ======================= Phase 0: QK GEMM (2-term) =====================
    {
        const int wm = wid & 3, wn = wid >> 2;   // warp tile 32m x 32n
        float acc[2][4][4];
        #pragma unroll
        for (int i = 0; i < 2; i++)
            #pragma unroll
            for (int j = 0; j < 4; j++)
                #pragma unroll
                for (int e = 0; e < 4; e++) acc[i][j][e] = 0.f;

        load_chunk_qk(sbase, tid, 0, bofs);
        load_chunk_qk(sbase + STAGE_QK, tid, 32, bofs);

        for (int c = 0; c < 16; c++) {
            if (c < 15) { CP_WAIT_GROUP(1); } else { CP_WAIT_GROUP(0); }
            __syncthreads();
            if (c + 2 < 16)
                load_chunk_qk(sbase + ((c+2) % 3)*STAGE_QK, tid, (c+2)*32, bofs);

            const uint32_t sb = sbase + (c % 3)*STAGE_QK;
            #pragma unroll
            for (int ks = 0; ks < 2; ks++) {
                uint32_t ah[2][4], al[2][4], bhf[4][2];
                #pragma unroll
                for (int tm = 0; tm < 2; tm++) {
                    uint32_t ra = sb + (wm*32 + tm*16 + (lmat&1)*8 + lrow)*ROWB + ks*32 + (lmat>>1)*16;
                    ldsm4(ah[tm][0], ah[tm][1], ah[tm][2], ah[tm][3], ra);
                    ldsm4(al[tm][0], al[tm][1], al[tm][2], al[tm][3], ra + SEG);
                }
                #pragma unroll
                for (int tp = 0; tp < 2; tp++) {
                    uint32_t rb = sb + 2*SEG + (wn*32 + (tp*2 + (lmat>>1))*8 + lrow)*ROWB + ks*32 + (lmat&1)*16;
                    ldsm4(bhf[tp*2][0], bhf[tp*2][1], bhf[tp*2+1][0], bhf[tp*2+1][1], rb);
                }
                #pragma unroll
                for (int tm = 0; tm < 2; tm++)
                    #pragma unroll
                    for (int tn = 0; tn < 4; tn++) {
                        mma_f16(acc[tm][tn], ah[tm][0], ah[tm][1], ah[tm][2], ah[tm][3], bhf[tn][0], bhf[tn][1]);
                        mma_f16(acc[tm][tn], al[tm][0], al[tm][1], al[tm][2], al[tm][3], bhf[tn][0], bhf[tn][1]);
                    }
            }
        }
        __syncthreads();   // all stage-0 reads done before sq/sk overlay

        // Epilogue: bias, pack (hi,lo) into smem sq/sk (overlays stages).
        #pragma unroll
        for (int tm = 0; tm < 2; tm++) {
            int mrow = wm*32 + tm*16 + g;
            float bias0 = g_bias[mrow];
            float bias1 = g_bias[mrow + 8];
            #pragma unroll
            for (int tn = 0; tn < 4; tn++) {
                int w = wn*32 + tn*8 + q*2;  // even
                uint32_t p0 = pack_hilo(acc[tm][tn][0] + bias0);
                uint32_t p1 = pack_hilo(acc[tm][tn][1] + bias0);
                uint32_t p2 = pack_hilo(acc[tm][tn][2] + bias1);
                uint32_t p3 = pack_hilo(acc[tm][tn][3] + bias1);
                #pragma unroll
                for (int rr = 0; rr < 2; rr++) {
                    int oc = mrow + rr*8;
                    uint32_t pa = rr ? p2 : p0;
                    uint32_t pb = rr ? p3 : p1;
                    if (oc < 64) {
                        int i = oc*2 + (w >> 6), cc = w & 63;
                        *(uint2*)(smem + AOFF_Q + i*AQK_ROWB + cc*4) = make_uint2(pa, pb);
                    } else {
                        int cq = oc - 64, cc = w >> 1;
                        *(uint32_t*)(smem + AOFF_K + cq*AQK_ROWB + cc*4)        = pa;
                        *(uint32_t*)(smem + AOFF_K + (64 + cq)*AQK_ROWB + cc*4) = pb;
                    }
                }
            }
        }
    }
    __syncthreads();

    const int wi = wid & 3;    // i 32-tile
    const int wj = wid >> 2;   // m 32-col / c 16-col group

    // ======================= Phase 1: energy (3-term) ======================
    {
        float e[2][4][4];
        #pragma unroll
        for (int a1 = 0; a1 < 2; a1++)
            #pragma unroll
            for (int a2 = 0; a2 < 4; a2++)
                #pragma unroll
                for (int a3 = 0; a3 < 4; a3++) e[a1][a2][a3] = 0.f;

        #pragma unroll
        for (int ks = 0; ks < 4; ks++) {
            uint32_t ah[2][4], al[2][4], bh_[4][2], bl_[4][2];
            #pragma unroll
            for (int ti = 0; ti < 2; ti++) {
                uint32_t ra = AOFF_Q + (wi*32 + ti*16 + g)*AQK_ROWB + ks*64 + q*8;
                uint2 w00 = *(const uint2*)(smem + ra);
                uint2 w10 = *(const uint2*)(smem + ra + 8*AQK_ROWB);
                uint2 w01 = *(const uint2*)(smem + ra + 32);
                uint2 w11 = *(const uint2*)(smem + ra + 8*AQK_ROWB + 32);
                ah[ti][0] = prmt(w00.x, w00.y, 0x5410); al[ti][0] = prmt(w00.x, w00.y, 0x7632);
                ah[ti][1] = prmt(w10.x, w10.y, 0x5410); al[ti][1] = prmt(w10.x, w10.y, 0x7632);
                ah[ti][2] = prmt(w01.x, w01.y, 0x5410); al[ti][2] = prmt(w01.x, w01.y, 0x7632);
                ah[ti][3] = prmt(w11.x, w11.y, 0x5410); al[ti][3] = prmt(w11.x, w11.y, 0x7632);
            }
            #pragma unroll
            for (int tn = 0; tn < 4; tn++) {
                uint32_t rb = AOFF_K + (wj*32 + tn*8 + g)*AQK_ROWB + ks*64 + q*8;
                uint2 u0 = *(const uint2*)(smem + rb);
                uint2 u1 = *(const uint2*)(smem + rb + 32);
                bh_[tn][0] = prmt(u0.x, u0.y, 0x5410); bl_[tn][0] = prmt(u0.x, u0.y, 0x7632);
                bh_[tn][1] = prmt(u1.x, u1.y, 0x5410); bl_[tn][1] = prmt(u1.x, u1.y, 0x7632);
            }
            #pragma unroll
            for (int ti = 0; ti < 2; ti++)
                #pragma unroll
                for (int tn = 0; tn < 4; tn++) {
                    mma_f16(e[ti][tn], ah[ti][0], ah[ti][1], ah[ti][2], ah[ti][3], bh_[tn][0], bh_[tn][1]);
                    mma_f16(e[ti][tn], al[ti][0], al[ti][1], al[ti][2], al[ti][3], bh_[tn][0], bh_[tn][1]);
                    mma_f16(e[ti][tn], ah[ti][0], ah[ti][1], ah[ti][2], ah[ti][3], bl_[tn][0], bl_[tn][1]);
                }
        }
        float* Ef = (float*)(smem + AOFF_E);
        #pragma unroll
        for (int ti = 0; ti < 2; ti++)
            #pragma unroll
            for (int tn = 0; tn < 4; tn++) {
                int ri = wi*32 + ti*16 + g, cj = wj*32 + tn*8 + 2*q;
                *(float2*)&Ef[ri*AE_STRIDE + cj]     = make_float2(e[ti][tn][0], e[ti][tn][1]);
                *(float2*)&Ef[(ri+8)*AE_STRIDE + cj] = make_float2(e[ti][tn][2], e[ti][tn][3]);
            }
    }
    __syncthreads();

    // ======================= Phase 2: softmax + pack A =====================
    {
        float* Ef = (float*)(smem + AOFF_E);
        int i = tid >> 2, qt = tid & 3;
        float* row = Ef + i*AE_STRIDE + qt*32;
        float mx = -1e30f;
        #pragma unroll 8
        for (int j = 0; j < 32; j++) mx = fmaxf(mx, row[j]);
        mx = fmaxf(mx, __shfl_xor_sync(0xFFFFFFFFu, mx, 1));
        mx = fmaxf(mx, __shfl_xor_sync(0xFFFFFFFFu, mx, 2));
        float s = 0.f;
        #pragma unroll 8
        for (int j = 0; j < 32; j++) { float p = __expf(row[j] - mx); row[j] = p; s += p; }
        s += __shfl_xor_sync(0xFFFFFFFFu, s, 1);
        s += __shfl_xor_sync(0xFFFFFFFFu, s, 2);
        float inv = 1.f / s;
        uint32_t* arow = (uint32_t*)(smem + AOFF_A + i*AA_ROWB + qt*64);
        #pragma unroll 8
        for (int j = 0; j < 32; j += 2)
            arow[j >> 1] = pack2h(row[j]*inv, row[j+1]*inv);
    }
    __syncthreads();

    // ======================= Phase 3: out = A @ V (8 chunks of 64 ch) ======
    float* STf = (float*)(smem + AOFF_ST);
    for (int ci = 0; ci < 8; ci++) {
        if (ci < 7) { CP_WAIT_GROUP(1); } else { CP_WAIT_GROUP(0); }
        __syncthreads();   // vb[ci&1] ready; STf free

        const uint32_t vb = AOFF_V + (ci & 1)*AV_BUFB;
        float o[2][2][4];
        #pragma unroll
        for (int a1 = 0; a1 < 2; a1++)
            #pragma unroll
            for (int a2 = 0; a2 < 2; a2++)
                #pragma unroll
                for (int a3 = 0; a3 < 4; a3++) o[a1][a2][a3] = 0.f;

        #pragma unroll
        for (int ks = 0; ks < 8; ks++) {
            uint32_t a0[2], a1r[2], a2[2], a3[2], b0[2], b1[2];
            #pragma unroll
            for (int ti = 0; ti < 2; ti++) {
                uint32_t ra = AOFF_A + (wi*32 + ti*16 + g)*AA_ROWB + ks*32 + q*4;
                a0[ti]  = *(const uint32_t*)(smem + ra);
                a1r[ti] = *(const uint32_t*)(smem + ra + 8*AA_ROWB);
                a2[ti]  = *(const uint32_t*)(smem + ra + 16);
                a3[ti]  = *(const uint32_t*)(smem + ra + 8*AA_ROWB + 16);
            }
            #pragma unroll
            for (int tn = 0; tn < 2; tn++) {
                uint32_t rb = vb + (wj*16 + tn*8 + g)*AV_ROWB + ks*32 + q*4;
                b0[tn] = *(const uint32_t*)(smem + rb);
                b1[tn] = *(const uint32_t*)(smem + rb + 16);
            }
            #pragma unroll
            for (int ti = 0; ti < 2; ti++)
                #pragma unroll
                for (int tn = 0; tn < 2; tn++)
                    mma_f16(o[ti][tn], a0[ti], a1r[ti], a2[ti], a3[ti], b0[tn], b1[tn]);
        }

        // stage out[i][c'] -> ST[c'][i]
        #pragma unroll
        for (int ti = 0; ti < 2; ti++)
            #pragma unroll
            for (int tn = 0; tn < 2; tn++) {
                int ri = wi*32 + ti*16 + g, cj = wj*16 + tn*8 + 2*q;
                STf[cj*AST_STRIDE + ri]          = o[ti][tn][0];
                STf[(cj+1)*AST_STRIDE + ri]      = o[ti][tn][1];
                STf[cj*AST_STRIDE + ri + 8]      = o[ti][tn][2];
                STf[(cj+1)*AST_STRIDE + ri + 8]  = o[ti][tn][3];
            }
        __syncthreads();   // all vb reads + ST writes complete

        if (ci + 2 < 8) att_load_v(sbase + vb, tid, b, h, (ci+2)*64);

        // coalesced writeback: out[b][c][h][i] = gma*o + x
        #pragma unroll
        for (int rr = 0; rr < 4; rr++) {
            int r = wid*4 + rr;
            int c = ci*64 + r;
            size_t gofs = (((size_t)b*Cc + c)*Hh + h)*Ww + lane*4;
            float4 xr = *(const float4*)(x + gofs);
            float4 ov = *(const float4*)(STf + r*AST_STRIDE + lane*4);
            *(float4*)(outp + gofs) = make_float4(gma*ov.x + xr.x, gma*ov.y + xr.y,
                                                  gma*ov.z + xr.z, gma*ov.w + xr.w);
        }
    }
}

// ---------------------------------------------------------------------------
extern "C" void kernel_launch(void* const* d_in, const int* in_sizes, int n_in,
                              void* d_out, int out_size)
{
    (void)in_sizes; (void)n_in; (void)out_size;
    const float* x     = (const float*)d_in[0];
    const float* Wq    = (const float*)d_in[1];
    const float* bq    = (const float*)d_in[2];
    const float* Wk    = (const float*)d_in[3];
    const float* bk    = (const float*)d_in[4];
    const float* Wv    = (const float*)d_in[5];
    const float* bv    = (const float*)d_in[6];
    const float* gamma = (const float*)d_in[7];
    float* out = (float*)d_out;

    dim3 gx(HW/64, Cc/64, Bn);
    prep_all<<<gx, 256>>>(x, Wq, bq, Wk, bk, Wv, bv);

    cudaFuncSetAttribute(qkv_gemm_v, cudaFuncAttributeMaxDynamicSharedMemorySize, SM_V);
    qkv_gemm_v<<<dim3(4, 128, Bn), 256, SM_V>>>();

    cudaFuncSetAttribute(attn_kernel, cudaFuncAttributeMaxDynamicSharedMemorySize, ATT_SMEM);
    attn_kernel<<<Bn*Hh, 512, ATT_SMEM>>>(x, gamma, out);
}

// round 16
// speedup vs baseline: 1.3182x; 1.1354x over previous
#include <cuda_runtime.h>
#include <cuda_fp16.h>
#include <cstdint>

#define Bn 8
#define Cc 512
#define CQ 64
#define Hh 128
#define Ww 128
#define HW (Hh*Ww)   // 16384

// ---------------------------------------------------------------------------
// Device scratch
// ---------------------------------------------------------------------------
__device__ __half g_v16[(size_t)Bn*Cc*HW];                // [b][c][s] fp16 single
__device__ __half g_xt_hi[(size_t)Bn*HW*Cc];              // xT[b][s][ch] fp16 single
__device__ __half g_w_hi[640*Cc];
__device__ __half g_w_lo[640*Cc];
__device__ float g_bias[640];

// ---------------------------------------------------------------------------
// helpers
// ---------------------------------------------------------------------------
__device__ __forceinline__ uint32_t smem_u32(const void* p) {
    uint32_t a;
    asm("{ .reg .u64 t; cvta.to.shared.u64 t, %1; cvt.u32.u64 %0, t; }" : "=r"(a) : "l"(p));
    return a;
}
__device__ __forceinline__ void cp16(uint32_t dst, const void* src) {
    asm volatile("cp.async.cg.shared.global [%0], [%1], 16;" :: "r"(dst), "l"(src));
}
#define CP_COMMIT()      asm volatile("cp.async.commit_group;" ::: "memory")
#define CP_WAIT_GROUP(n) asm volatile("cp.async.wait_group %0;" :: "n"(n) : "memory")

__device__ __forceinline__ void mma_f16(float c[4], uint32_t a0, uint32_t a1, uint32_t a2, uint32_t a3,
                                        uint32_t b0, uint32_t b1) {
    asm volatile("mma.sync.aligned.m16n8k16.row.col.f32.f16.f16.f32 "
                 "{%0,%1,%2,%3}, {%4,%5,%6,%7}, {%8,%9}, {%0,%1,%2,%3};"
                 : "+f"(c[0]), "+f"(c[1]), "+f"(c[2]), "+f"(c[3])
                 : "r"(a0), "r"(a1), "r"(a2), "r"(a3), "r"(b0), "r"(b1));
}
__device__ __forceinline__ void ldsm4(uint32_t& r0, uint32_t& r1, uint32_t& r2, uint32_t& r3,
                                      uint32_t addr) {
    asm volatile("ldmatrix.sync.aligned.m8n8.x4.shared.b16 {%0,%1,%2,%3}, [%4];"
                 : "=r"(r0), "=r"(r1), "=r"(r2), "=r"(r3) : "r"(addr));
}
__device__ __forceinline__ uint32_t prmt(uint32_t a, uint32_t b, uint32_t s) {
    uint32_t d;
    asm("prmt.b32 %0, %1, %2, %3;" : "=r"(d) : "r"(a), "r"(b), "r"(s));
    return d;
}
__device__ __forceinline__ uint32_t pack_hilo(float v) {
    __half h = __float2half_rn(v);
    float r = v - __half2float(h);
    __half l = __float2half_rn(r);
    return (uint32_t)__half_as_ushort(h) | ((uint32_t)__half_as_ushort(l) << 16);
}
__device__ __forceinline__ uint32_t pack2h(float a, float b) {
    __half ha = __float2half_rn(a), hb = __float2half_rn(b);
    return (uint32_t)__half_as_ushort(ha) | ((uint32_t)__half_as_ushort(hb) << 16);
}

// ---------------------------------------------------------------------------
// Prep: x[b][ch][s] -> xT fp16 [b][s][ch] (single). Vectorized + XOR-swizzled
// smem transpose (conflict-free both sides). 214 blocks also convert W hi/lo.
// ---------------------------------------------------------------------------
__global__ void __launch_bounds__(256) prep_all(
    const float* __restrict__ x,
    const float* __restrict__ Wq, const float* __restrict__ bq,
    const float* __restrict__ Wk, const float* __restrict__ bk,
    const float* __restrict__ Wv, const float* __restrict__ bv)
{
    __shared__ float st[64*64];
    const int b = blockIdx.z, ch0 = blockIdx.y * 64, s0 = blockIdx.x * 64;

    if (b == 0 && blockIdx.y == 0 && blockIdx.x < 214) {
        #pragma unroll
        for (int rr = 0; rr < 3; rr++) {
            int r = blockIdx.x * 3 + rr;
            if (r < 640) {
                const float* src; float bias;
                if (r < 64)       { src = Wq + (size_t)r*Cc;        bias = bq[r]; }
                else if (r < 128) { src = Wk + (size_t)(r-64)*Cc;   bias = bk[r-64]; }
                else              { src = Wv + (size_t)(r-128)*Cc;  bias = bv[r-128]; }
                if (threadIdx.x == 0) g_bias[r] = bias;
                for (int c = threadIdx.x; c < Cc; c += 256) {
                    float v = src[c];
                    __half h = __float2half_rn(v);
                    g_w_hi[(size_t)r*Cc + c] = h;
                    g_w_lo[(size_t)r*Cc + c] = __float2half_rn(v - __half2float(h));
                }
            }
        }
    }

    // load 64x64 fp32 tile, float4, XOR swizzle s' = s ^ 4*(ch>>3)
    const float* xb = x + ((size_t)b*Cc + ch0)*HW + s0;
    #pragma unroll
    for (int i = threadIdx.x; i < 1024; i += 256) {
        int ch = i >> 4, s4 = (i & 15) << 2;
        int sw = s4 ^ ((ch >> 3) << 2);
        *(float4*)&st[ch*64 + sw] = *(const float4*)(xb + (size_t)ch*HW + s4);
    }
    __syncthreads();

    // transpose-convert: each u covers (s, 8 channels) -> one uint4 store
    #pragma unroll
    for (int u = threadIdx.x; u < 512; u += 256) {
        int s = u >> 3, c8 = (u & 7) * 8;
        int sw = s ^ ((c8 >> 3) << 2);   // (c8+j)>>3 == c8>>3 for j<8
        uint32_t hi[4];
        #pragma unroll
        for (int j = 0; j < 4; j++) {
            float a = st[(c8 + 2*j    )*64 + sw];
            float c = st[(c8 + 2*j + 1)*64 + sw];
            hi[j] = pack2h(a, c);
        }
        size_t off = ((size_t)(b*HW + s0 + s))*Cc + ch0 + c8;
        *(uint4*)(g_xt_hi + off) = make_uint4(hi[0], hi[1], hi[2], hi[3]);
    }
}

// ---------------------------------------------------------------------------
// V GEMM: rows 128..639 of W, 1-term fp16 (hi only). K chunks of 64,
// 256 threads, 2 CTAs/SM, ldmatrix loads, single-barrier pipeline.
// ---------------------------------------------------------------------------
#define V_ROWB 144
#define V_SEG  18432
#define STAGE_V (2*V_SEG)
#define SM_V (3*STAGE_V)       // 110592

__device__ __forceinline__ void load_chunk_v(uint32_t sb, int tid, int k0, int m0, size_t bofs)
{
    const __half* srcs[2] = {
        g_w_hi + (size_t)(128 + m0)*Cc + k0,
        g_xt_hi + bofs + k0 };
    #pragma unroll
    for (int i = tid; i < 2048; i += 256) {
        int seg = i >> 10;
        int r = (i & 1023) >> 3, u = i & 7;
        cp16(sb + seg*V_SEG + r*V_ROWB + u*16, srcs[seg] + (size_t)r*Cc + u*8);
    }
    CP_COMMIT();
}

__global__ void __launch_bounds__(256, 2) qkv_gemm_v()
{
    extern __shared__ char smem[];
    const uint32_t sbase = smem_u32(smem);
    const int tid = threadIdx.x, wid = tid >> 5, lane = tid & 31;
    const int g = lane >> 2, q = lane & 3;
    const int m0 = blockIdx.x * 128;
    const int n0 = blockIdx.y * 128;
    const int b  = blockIdx.z;
    const size_t bofs = ((size_t)b*HW + n0)*Cc;
    const int wm = wid & 1, wn = wid >> 1;
    const int lmat = lane >> 3, lrow = lane & 7;

    float acc[4][4][4];
    #pragma unroll
    for (int i = 0; i < 4; i++)
        #pragma unroll
        for (int j = 0; j < 4; j++)
            #pragma unroll
            for (int e = 0; e < 4; e++) acc[i][j][e] = 0.f;

    load_chunk_v(sbase, tid, 0, m0, bofs);
    load_chunk_v(sbase + STAGE_V, tid, 64, m0, bofs);

    for (int c = 0; c < 8; c++) {
        if (c < 7) { CP_WAIT_GROUP(1); } else { CP_WAIT_GROUP(0); }
        __syncthreads();
        if (c + 2 < 8)
            load_chunk_v(sbase + ((c+2) % 3)*STAGE_V, tid, (c+2)*64, m0, bofs);

        const uint32_t sb = sbase + (c % 3)*STAGE_V;
        #pragma unroll
        for (int ks = 0; ks < 4; ks++) {
            uint32_t ah[4][4], bh[4][2];
            #pragma unroll
            for (int tm = 0; tm < 4; tm++) {
                uint32_t ra = sb + (wm*64 + tm*16 + (lmat&1)*8 + lrow)*V_ROWB + ks*32 + (lmat>>1)*16;
                ldsm4(ah[tm][0], ah[tm][1], ah[tm][2], ah[tm][3], ra);
            }
            #pragma unroll
            for (int tp = 0; tp < 2; tp++) {
                uint32_t rb = sb + V_SEG + (wn*32 + (tp*2 + (lmat>>1))*8 + lrow)*V_ROWB + ks*32 + (lmat&1)*16;
                ldsm4(bh[tp*2][0], bh[tp*2][1], bh[tp*2+1][0], bh[tp*2+1][1], rb);
            }
            #pragma unroll
            for (int tm = 0; tm < 4; tm++)
                #pragma unroll
                for (int tn = 0; tn < 4; tn++)
                    mma_f16(acc[tm][tn], ah[tm][0], ah[tm][1], ah[tm][2], ah[tm][3], bh[tn][0], bh[tn][1]);
        }
    }

    #pragma unroll
    for (int tm = 0; tm < 4; tm++) {
        int cv = m0 + wm*64 + tm*16 + g;
        float bias0 = g_bias[128 + cv];
        float bias1 = g_bias[128 + cv + 8];
        #pragma unroll
        for (int tn = 0; tn < 4; tn++) {
            int n = n0 + wn*32 + tn*8 + q*2;
            uint32_t pa = pack2h(acc[tm][tn][0] + bias0, acc[tm][tn][1] + bias0);
            uint32_t pb = pack2h(acc[tm][tn][2] + bias1, acc[tm][tn][3] + bias1);
            *(uint32_t*)&g_v16[((size_t)b*Cc + cv)*HW + n]     = pa;
            *(uint32_t*)&g_v16[((size_t)b*Cc + cv + 8)*HW + n] = pb;
        }
    }
}

// ---------------------------------------------------------------------------
// Fused QK-GEMM + attention. One CTA per (b,h), 512 threads.
// Phase 0: 2-term QK (W hi/lo, x fp16 single). Stage = Ah|Al|Bh (3 segs).
// ---------------------------------------------------------------------------
#define ROWB 80
#define SEG  10240
#define STAGE_QK (3*SEG)       // 30720

#define AQK_ROWB 272
#define AA_ROWB  272
#define AV_ROWB  272
#define AE_STRIDE 132
#define AST_STRIDE 132
#define AOFF_Q   0
#define AOFF_K   34816
#define AOFF_A   0
#define AOFF_E   92160
#define AOFF_ST  92160
#define AOFF_V   161792
#define AV_BUFB  17408         // 64 rows * 272
#define ATT_SMEM 196608

__device__ __forceinline__ void load_chunk_qk(uint32_t sb, int tid, int k0, size_t bofs)
{
    const __half* srcs[3] = { g_w_hi + k0, g_w_lo + k0, g_xt_hi + bofs + k0 };
    #pragma unroll
    for (int i = tid; i < 1536; i += 512) {
        int seg = i / 512;
        int r = (i & 511) >> 2, u = i & 3;
        cp16(sb + seg*SEG + r*ROWB + u*16, srcs[seg] + (size_t)r*Cc + u*8);
    }
    CP_COMMIT();
}

__device__ __forceinline__ void att_load_v(uint32_t sbv, int tid, int b, int h, int cc)
{
    const __half* src0 = g_v16 + (((size_t)b*Cc + cc)*Hh + h)*Ww;
    #pragma unroll
    for (int i = tid; i < 1024; i += 512) {
        int r = i >> 4, u = i & 15;
        cp16(sbv + r*AV_ROWB + u*16, src0 + (size_t)r*HW + u*8);
    }
    CP_COMMIT();
}

__global__ void __launch_bounds__(512, 1) attn_kernel(
    const float* __restrict__ x,
    const float* __restrict__ gamma_p,
    float* __restrict__ outp)
{
    extern __shared__ char smem[];
    const uint32_t sbase = smem_u32(smem);
    const int tid = threadIdx.x, wid = tid >> 5, lane = tid & 31;
    const int g = lane >> 2, q = lane & 3;
    const int bh = blockIdx.x;
    const int b = bh >> 7, h = bh & 127;
    const float gma = gamma_p[0];
    const size_t bofs = ((size_t)b*HW + h*128)*Cc;
    const int lmat = lane >> 3, lrow = lane & 7;

    att_load_v(sbase + AOFF_V, tid, b, h, 0);
    att_load_v(sbase + AOFF_V + AV_BUFB, tid, b, h, 64);

    // ======================= Phase 0: QK GEMM (2-term) =====================
    {
        const int wm = wid & 3, wn = wid >> 2;
        float acc[2][4][4];
        #pragma unroll
        for (int i = 0; i < 2; i++)
            #pragma unroll
            for (int j = 0; j < 4; j++)
                #pragma unroll
                for (int e = 0; e < 4; e++) acc[i][j][e] = 0.f;

        load_chunk_qk(sbase, tid, 0, bofs);
        load_chunk_qk(sbase + STAGE_QK, tid, 32, bofs);

        for (int c = 0; c < 16; c++) {
            if (c < 15) { CP_WAIT_GROUP(1); } else { CP_WAIT_GROUP(0); }
            __syncthreads();
            if (c + 2 < 16)
                load_chunk_qk(sbase + ((c+2) % 3)*STAGE_QK, tid, (c+2)*32, bofs);

            const uint32_t sb = sbase + (c % 3)*STAGE_QK;
            #pragma unroll
            for (int ks = 0; ks < 2; ks++) {
                uint32_t ah[2][4], al[2][4], bhf[4][2];
                #pragma unroll
                for (int tm = 0; tm < 2; tm++) {
                    uint32_t ra = sb + (wm*32 + tm*16 + (lmat&1)*8 + lrow)*ROWB + ks*32 + (lmat>>1)*16;
                    ldsm4(ah[tm][0], ah[tm][1], ah[tm][2], ah[tm][3], ra);
                    ldsm4(al[tm][0], al[tm][1], al[tm][2], al[tm][3], ra + SEG);
                }
                #pragma unroll
                for (int tp = 0; tp < 2; tp++) {
                    uint32_t rb = sb + 2*SEG + (wn*32 + (tp*2 + (lmat>>1))*8 + lrow)*ROWB + ks*32 + (lmat&1)*16;
                    ldsm4(bhf[tp*2][0], bhf[tp*2][1], bhf[tp*2+1][0], bhf[tp*2+1][1], rb);
                }
                #pragma unroll
                for (int tm = 0; tm < 2; tm++)
                    #pragma unroll
                    for (int tn = 0; tn < 4; tn++) {
                        mma_f16(acc[tm][tn], ah[tm][0], ah[tm][1], ah[tm][2], ah[tm][3], bhf[tn][0], bhf[tn][1]);
                        mma_f16(acc[tm][tn], al[tm][0], al[tm][1], al[tm][2], al[tm][3], bhf[tn][0], bhf[tn][1]);
                    }
            }
        }
        __syncthreads();

        #pragma unroll
        for (int tm = 0; tm < 2; tm++) {
            int mrow = wm*32 + tm*16 + g;
            float bias0 = g_bias[mrow];
            float bias1 = g_bias[mrow + 8];
            #pragma unroll
            for (int tn = 0; tn < 4; tn++) {
                int w = wn*32 + tn*8 + q*2;
                uint32_t p0 = pack_hilo(acc[tm][tn][0] + bias0);
                uint32_t p1 = pack_hilo(acc[tm][tn][1] + bias0);
                uint32_t p2 = pack_hilo(acc[tm][tn][2] + bias1);
                uint32_t p3 = pack_hilo(acc[tm][tn][3] + bias1);
                #pragma unroll
                for (int rr = 0; rr < 2; rr++) {
                    int oc = mrow + rr*8;
                    uint32_t pa = rr ? p2 : p0;
                    uint32_t pb = rr ? p3 : p1;
                    if (oc < 64) {
                        int i = oc*2 + (w >> 6), cc = w & 63;
                        *(uint2*)(smem + AOFF_Q + i*AQK_ROWB + cc*4) = make_uint2(pa, pb);
                    } else {
                        int cq = oc - 64, cc = w >> 1;
                        *(uint32_t*)(smem + AOFF_K + cq*AQK_ROWB + cc*4)        = pa;
                        *(uint32_t*)(smem + AOFF_K + (64 + cq)*AQK_ROWB + cc*4) = pb;
                    }
                }
            }
        }
    }
    __syncthreads();

    const int wi = wid & 3;
    const int wj = wid >> 2;

    // ======================= Phase 1: energy (3-term) ======================
    {
        float e[2][4][4];
        #pragma unroll
        for (int a1 = 0; a1 < 2; a1++)
            #pragma unroll
            for (int a2 = 0; a2 < 4; a2++)
                #pragma unroll
                for (int a3 = 0; a3 < 4; a3++) e[a1][a2][a3] = 0.f;

        #pragma unroll
        for (int ks = 0; ks < 4; ks++) {
            uint32_t ah[2][4], al[2][4], bh_[4][2], bl_[4][2];
            #pragma unroll
            for (int ti = 0; ti < 2; ti++) {
                uint32_t ra = AOFF_Q + (wi*32 + ti*16 + g)*AQK_ROWB + ks*64 + q*8;
                uint2 w00 = *(const uint2*)(smem + ra);
                uint2 w10 = *(const uint2*)(smem + ra + 8*AQK_ROWB);
                uint2 w01 = *(const uint2*)(smem + ra + 32);
                uint2 w11 = *(const uint2*)(smem + ra + 8*AQK_ROWB + 32);
                ah[ti][0] = prmt(w00.x, w00.y, 0x5410); al[ti][0] = prmt(w00.x, w00.y, 0x7632);
                ah[ti][1] = prmt(w10.x, w10.y, 0x5410); al[ti][1] = prmt(w10.x, w10.y, 0x7632);
                ah[ti][2] = prmt(w01.x, w01.y, 0x5410); al[ti][2] = prmt(w01.x, w01.y, 0x7632);
                ah[ti][3] = prmt(w11.x, w11.y, 0x5410); al[ti][3] = prmt(w11.x, w11.y, 0x7632);
            }
            #pragma unroll
            for (int tn = 0; tn < 4; tn++) {
                uint32_t rb = AOFF_K + (wj*32 + tn*8 + g)*AQK_ROWB + ks*64 + q*8;
                uint2 u0 = *(const uint2*)(smem + rb);
                uint2 u1 = *(const uint2*)(smem + rb + 32);
                bh_[tn][0] = prmt(u0.x, u0.y, 0x5410); bl_[tn][0] = prmt(u0.x, u0.y, 0x7632);
                bh_[tn][1] = prmt(u1.x, u1.y, 0x5410); bl_[tn][1] = prmt(u1.x, u1.y, 0x7632);
            }
            #pragma unroll
            for (int ti = 0; ti < 2; ti++)
                #pragma unroll
                for (int tn = 0; tn < 4; tn++) {
                    mma_f16(e[ti][tn], ah[ti][0], ah[ti][1], ah[ti][2], ah[ti][3], bh_[tn][0], bh_[tn][1]);
                    mma_f16(e[ti][tn], al[ti][0], al[ti][1], al[ti][2], al[ti][3], bh_[tn][0], bh_[tn][1]);
                    mma_f16(e[ti][tn], ah[ti][0], ah[ti][1], ah[ti][2], ah[ti][3], bl_[tn][0], bl_[tn][1]);
                }
        }
        float* Ef = (float*)(smem + AOFF_E);
        #pragma unroll
        for (int ti = 0; ti < 2; ti++)
            #pragma unroll
            for (int tn = 0; tn < 4; tn++) {
                int ri = wi*32 + ti*16 + g, cj = wj*32 + tn*8 + 2*q;
                *(float2*)&Ef[ri*AE_STRIDE + cj]     = make_float2(e[ti][tn][0], e[ti][tn][1]);
                *(float2*)&Ef[(ri+8)*AE_STRIDE + cj] = make_float2(e[ti][tn][2], e[ti][tn][3]);
            }
    }
    __syncthreads();

    // ======================= Phase 2: softmax + pack A =====================
    {
        float* Ef = (float*)(smem + AOFF_E);
        int i = tid >> 2, qt = tid & 3;
        float* row = Ef + i*AE_STRIDE + qt*32;
        float mx = -1e30f;
        #pragma unroll 8
        for (int j = 0; j < 32; j++) mx = fmaxf(mx, row[j]);
        mx = fmaxf(mx, __shfl_xor_sync(0xFFFFFFFFu, mx, 1));
        mx = fmaxf(mx, __shfl_xor_sync(0xFFFFFFFFu, mx, 2));
        float s = 0.f;
        #pragma unroll 8
        for (int j = 0; j < 32; j++) { float p = __expf(row[j] - mx); row[j] = p; s += p; }
        s += __shfl_xor_sync(0xFFFFFFFFu, s, 1);
        s += __shfl_xor_sync(0xFFFFFFFFu, s, 2);
        float inv = 1.f / s;
        uint32_t* arow = (uint32_t*)(smem + AOFF_A + i*AA_ROWB + qt*64);
        #pragma unroll 8
        for (int j = 0; j < 32; j += 2)
            arow[j >> 1] = pack2h(row[j]*inv, row[j+1]*inv);
    }
    __syncthreads();

    // ======================= Phase 3: out = A @ V (8 chunks of 64 ch) ======
    float* STf = (float*)(smem + AOFF_ST);
    for (int ci = 0; ci < 8; ci++) {
        if (ci < 7) { CP_WAIT_GROUP(1); } else { CP_WAIT_GROUP(0); }
        __syncthreads();

        const uint32_t vb = AOFF_V + (ci & 1)*AV_BUFB;
        float o[2][2][4];
        #pragma unroll
        for (int a1 = 0; a1 < 2; a1++)
            #pragma unroll
            for (int a2 = 0; a2 < 2; a2++)
                #pragma unroll
                for (int a3 = 0; a3 < 4; a3++) o[a1][a2][a3] = 0.f;

        #pragma unroll
        for (int ks = 0; ks < 8; ks++) {
            uint32_t a0[2], a1r[2], a2[2], a3[2], b0[2], b1[2];
            #pragma unroll
            for (int ti = 0; ti < 2; ti++) {
                uint32_t ra = AOFF_A + (wi*32 + ti*16 + g)*AA_ROWB + ks*32 + q*4;
                a0[ti]  = *(const uint32_t*)(smem + ra);
                a1r[ti] = *(const uint32_t*)(smem + ra + 8*AA_ROWB);
                a2[ti]  = *(const uint32_t*)(smem + ra + 16);
                a3[ti]  = *(const uint32_t*)(smem + ra + 8*AA_ROWB + 16);
            }
            #pragma unroll
            for (int tn = 0; tn < 2; tn++) {
                uint32_t rb = vb + (wj*16 + tn*8 + g)*AV_ROWB + ks*32 + q*4;
                b0[tn] = *(const uint32_t*)(smem + rb);
                b1[tn] = *(const uint32_t*)(smem + rb + 16);
            }
            #pragma unroll
            for (int ti = 0; ti < 2; ti++)
                #pragma unroll
                for (int tn = 0; tn < 2; tn++)
                    mma_f16(o[ti][tn], a0[ti], a1r[ti], a2[ti], a3[ti], b0[tn], b1[tn]);
        }

        #pragma unroll
        for (int ti = 0; ti < 2; ti++)
            #pragma unroll
            for (int tn = 0; tn < 2; tn++) {
                int ri = wi*32 + ti*16 + g, cj = wj*16 + tn*8 + 2*q;
                STf[cj*AST_STRIDE + ri]          = o[ti][tn][0];
                STf[(cj+1)*AST_STRIDE + ri]      = o[ti][tn][1];
                STf[cj*AST_STRIDE + ri + 8]      = o[ti][tn][2];
                STf[(cj+1)*AST_STRIDE + ri + 8]  = o[ti][tn][3];
            }
        __syncthreads();

        if (ci + 2 < 8) att_load_v(sbase + vb, tid, b, h, (ci+2)*64);

        #pragma unroll
        for (int rr = 0; rr < 4; rr++) {
            int r = wid*4 + rr;
            int c = ci*64 + r;
            size_t gofs = (((size_t)b*Cc + c)*Hh + h)*Ww + lane*4;
            float4 xr = *(const float4*)(x + gofs);
            float4 ov = *(const float4*)(STf + r*AST_STRIDE + lane*4);
            *(float4*)(outp + gofs) = make_float4(gma*ov.x + xr.x, gma*ov.y + xr.y,
                                                  gma*ov.z + xr.z, gma*ov.w + xr.w);
        }
    }
}

// ---------------------------------------------------------------------------
extern "C" void kernel_launch(void* const* d_in, const int* in_sizes, int n_in,
                              void* d_out, int out_size)
{
    (void)in_sizes; (void)n_in; (void)out_size;
    const float* x     = (const float*)d_in[0];
    const float* Wq    = (const float*)d_in[1];
    const float* bq    = (const float*)d_in[2];
    const float* Wk    = (const float*)d_in[3];
    const float* bk    = (const float*)d_in[4];
    const float* Wv    = (const float*)d_in[5];
    const float* bv    = (const float*)d_in[6];
    const float* gamma = (const float*)d_in[7];
    float* out = (float*)d_out;

    dim3 gx(HW/64, Cc/64, Bn);
    prep_all<<<gx, 256>>>(x, Wq, bq, Wk, bk, Wv, bv);

    cudaFuncSetAttribute(qkv_gemm_v, cudaFuncAttributeMaxDynamicSharedMemorySize, SM_V);
    qkv_gemm_v<<<dim3(4, 128, Bn), 256, SM_V>>>();

    cudaFuncSetAttribute(attn_kernel, cudaFuncAttributeMaxDynamicSharedMemorySize, ATT_SMEM);
    attn_kernel<<<Bn*Hh, 512, ATT_SMEM>>>(x, gamma, out);
}

// round 17
// speedup vs baseline: 1.3423x; 1.0182x over previous
#include <cuda_runtime.h>
#include <cuda_fp16.h>
#include <cstdint>

#define Bn 8
#define Cc 512
#define CQ 64
#define Hh 128
#define Ww 128
#define HW (Hh*Ww)   // 16384

// ---------------------------------------------------------------------------
// Device scratch
// ---------------------------------------------------------------------------
__device__ __half g_v16[(size_t)Bn*Cc*HW];                // [b][c][s] fp16 single
__device__ __half g_xt_hi[(size_t)Bn*HW*Cc];              // xT[b][s][ch] fp16 single
__device__ __half g_w_hi[640*Cc];
__device__ __half g_w_lo[640*Cc];                         // kept for possible fallback; unused now
__device__ float g_bias[640];

// ---------------------------------------------------------------------------
// helpers
// ---------------------------------------------------------------------------
__device__ __forceinline__ uint32_t smem_u32(const void* p) {
    uint32_t a;
    asm("{ .reg .u64 t; cvta.to.shared.u64 t, %1; cvt.u32.u64 %0, t; }" : "=r"(a) : "l"(p));
    return a;
}
__device__ __forceinline__ void cp16(uint32_t dst, const void* src) {
    asm volatile("cp.async.cg.shared.global [%0], [%1], 16;" :: "r"(dst), "l"(src));
}
#define CP_COMMIT()      asm volatile("cp.async.commit_group;" ::: "memory")
#define CP_WAIT_GROUP(n) asm volatile("cp.async.wait_group %0;" :: "n"(n) : "memory")

__device__ __forceinline__ void mma_f16(float c[4], uint32_t a0, uint32_t a1, uint32_t a2, uint32_t a3,
                                        uint32_t b0, uint32_t b1) {
    asm volatile("mma.sync.aligned.m16n8k16.row.col.f32.f16.f16.f32 "
                 "{%0,%1,%2,%3}, {%4,%5,%6,%7}, {%8,%9}, {%0,%1,%2,%3};"
                 : "+f"(c[0]), "+f"(c[1]), "+f"(c[2]), "+f"(c[3])
                 : "r"(a0), "r"(a1), "r"(a2), "r"(a3), "r"(b0), "r"(b1));
}
__device__ __forceinline__ void ldsm4(uint32_t& r0, uint32_t& r1, uint32_t& r2, uint32_t& r3,
                                      uint32_t addr) {
    asm volatile("ldmatrix.sync.aligned.m8n8.x4.shared.b16 {%0,%1,%2,%3}, [%4];"
                 : "=r"(r0), "=r"(r1), "=r"(r2), "=r"(r3) : "r"(addr));
}
__device__ __forceinline__ uint32_t prmt(uint32_t a, uint32_t b, uint32_t s) {
    uint32_t d;
    asm("prmt.b32 %0, %1, %2, %3;" : "=r"(d) : "r"(a), "r"(b), "r"(s));
    return d;
}
__device__ __forceinline__ uint32_t pack_hilo(float v) {
    __half h = __float2half_rn(v);
    float r = v - __half2float(h);
    __half l = __float2half_rn(r);
    return (uint32_t)__half_as_ushort(h) | ((uint32_t)__half_as_ushort(l) << 16);
}
__device__ __forceinline__ uint32_t pack2h(float a, float b) {
    __half ha = __float2half_rn(a), hb = __float2half_rn(b);
    return (uint32_t)__half_as_ushort(ha) | ((uint32_t)__half_as_ushort(hb) << 16);
}

// ---------------------------------------------------------------------------
// Prep: x[b][ch][s] -> xT fp16 [b][s][ch]; W hi/lo; swizzled transpose.
// ---------------------------------------------------------------------------
__global__ void __launch_bounds__(256) prep_all(
    const float* __restrict__ x,
    const float* __restrict__ Wq, const float* __restrict__ bq,
    const float* __restrict__ Wk, const float* __restrict__ bk,
    const float* __restrict__ Wv, const float* __restrict__ bv)
{
    __shared__ float st[64*64];
    const int b = blockIdx.z, ch0 = blockIdx.y * 64, s0 = blockIdx.x * 64;

    if (b == 0 && blockIdx.y == 0 && blockIdx.x < 214) {
        #pragma unroll
        for (int rr = 0; rr < 3; rr++) {
            int r = blockIdx.x * 3 + rr;
            if (r < 640) {
                const float* src; float bias;
                if (r < 64)       { src = Wq + (size_t)r*Cc;        bias = bq[r]; }
                else if (r < 128) { src = Wk + (size_t)(r-64)*Cc;   bias = bk[r-64]; }
                else              { src = Wv + (size_t)(r-128)*Cc;  bias = bv[r-128]; }
                if (threadIdx.x == 0) g_bias[r] = bias;
                for (int c = threadIdx.x; c < Cc; c += 256) {
                    float v = src[c];
                    __half h = __float2half_rn(v);
                    g_w_hi[(size_t)r*Cc + c] = h;
                    g_w_lo[(size_t)r*Cc + c] = __float2half_rn(v - __half2float(h));
                }
            }
        }
    }

    const float* xb = x + ((size_t)b*Cc + ch0)*HW + s0;
    #pragma unroll
    for (int i = threadIdx.x; i < 1024; i += 256) {
        int ch = i >> 4, s4 = (i & 15) << 2;
        int sw = s4 ^ ((ch >> 3) << 2);
        *(float4*)&st[ch*64 + sw] = *(const float4*)(xb + (size_t)ch*HW + s4);
    }
    __syncthreads();

    #pragma unroll
    for (int u = threadIdx.x; u < 512; u += 256) {
        int s = u >> 3, c8 = (u & 7) * 8;
        int sw = s ^ ((c8 >> 3) << 2);
        uint32_t hi[4];
        #pragma unroll
        for (int j = 0; j < 4; j++) {
            float a = st[(c8 + 2*j    )*64 + sw];
            float c = st[(c8 + 2*j + 1)*64 + sw];
            hi[j] = pack2h(a, c);
        }
        size_t off = ((size_t)(b*HW + s0 + s))*Cc + ch0 + c8;
        *(uint4*)(g_xt_hi + off) = make_uint4(hi[0], hi[1], hi[2], hi[3]);
    }
}

// ---------------------------------------------------------------------------
// V GEMM: rows 128..639 of W, 1-term fp16 (hi only). K chunks of 64,
// 256 threads, 2 CTAs/SM, ldmatrix loads, single-barrier pipeline.
// ---------------------------------------------------------------------------
#define V_ROWB 144
#define V_SEG  18432
#define STAGE_V (2*V_SEG)
#define SM_V (3*STAGE_V)       // 110592

__device__ __forceinline__ void load_chunk_v(uint32_t sb, int tid, int k0, int m0, size_t bofs)
{
    const __half* srcs[2] = {
        g_w_hi + (size_t)(128 + m0)*Cc + k0,
        g_xt_hi + bofs + k0 };
    #pragma unroll
    for (int i = tid; i < 2048; i += 256) {
        int seg = i >> 10;
        int r = (i & 1023) >> 3, u = i & 7;
        cp16(sb + seg*V_SEG + r*V_ROWB + u*16, srcs[seg] + (size_t)r*Cc + u*8);
    }
    CP_COMMIT();
}

__global__ void __launch_bounds__(256, 2) qkv_gemm_v()
{
    extern __shared__ char smem[];
    const uint32_t sbase = smem_u32(smem);
    const int tid = threadIdx.x, wid = tid >> 5, lane = tid & 31;
    const int g = lane >> 2, q = lane & 3;
    const int m0 = blockIdx.x * 128;
    const int n0 = blockIdx.y * 128;
    const int b  = blockIdx.z;
    const size_t bofs = ((size_t)b*HW + n0)*Cc;
    const int wm = wid & 1, wn = wid >> 1;
    const int lmat = lane >> 3, lrow = lane & 7;

    float acc[4][4][4];
    #pragma unroll
    for (int i = 0; i < 4; i++)
        #pragma unroll
        for (int j = 0; j < 4; j++)
            #pragma unroll
            for (int e = 0; e < 4; e++) acc[i][j][e] = 0.f;

    load_chunk_v(sbase, tid, 0, m0, bofs);
    load_chunk_v(sbase + STAGE_V, tid, 64, m0, bofs);

    for (int c = 0; c < 8; c++) {
        if (c < 7) { CP_WAIT_GROUP(1); } else { CP_WAIT_GROUP(0); }
        __syncthreads();
        if (c + 2 < 8)
            load_chunk_v(sbase + ((c+2) % 3)*STAGE_V, tid, (c+2)*64, m0, bofs);

        const uint32_t sb = sbase + (c % 3)*STAGE_V;
        #pragma unroll
        for (int ks = 0; ks < 4; ks++) {
            uint32_t ah[4][4], bh[4][2];
            #pragma unroll
            for (int tm = 0; tm < 4; tm++) {
                uint32_t ra = sb + (wm*64 + tm*16 + (lmat&1)*8 + lrow)*V_ROWB + ks*32 + (lmat>>1)*16;
                ldsm4(ah[tm][0], ah[tm][1], ah[tm][2], ah[tm][3], ra);
            }
            #pragma unroll
            for (int tp = 0; tp < 2; tp++) {
                uint32_t rb = sb + V_SEG + (wn*32 + (tp*2 + (lmat>>1))*8 + lrow)*V_ROWB + ks*32 + (lmat&1)*16;
                ldsm4(bh[tp*2][0], bh[tp*2][1], bh[tp*2+1][0], bh[tp*2+1][1], rb);
            }
            #pragma unroll
            for (int tm = 0; tm < 4; tm++)
                #pragma unroll
                for (int tn = 0; tn < 4; tn++)
                    mma_f16(acc[tm][tn], ah[tm][0], ah[tm][1], ah[tm][2], ah[tm][3], bh[tn][0], bh[tn][1]);
        }
    }

    #pragma unroll
    for (int tm = 0; tm < 4; tm++) {
        int cv = m0 + wm*64 + tm*16 + g;
        float bias0 = g_bias[128 + cv];
        float bias1 = g_bias[128 + cv + 8];
        #pragma unroll
        for (int tn = 0; tn < 4; tn++) {
            int n = n0 + wn*32 + tn*8 + q*2;
            uint32_t pa = pack2h(acc[tm][tn][0] + bias0, acc[tm][tn][1] + bias0);
            uint32_t pb = pack2h(acc[tm][tn][2] + bias1, acc[tm][tn][3] + bias1);
            *(uint32_t*)&g_v16[((size_t)b*Cc + cv)*HW + n]     = pa;
            *(uint32_t*)&g_v16[((size_t)b*Cc + cv + 8)*HW + n] = pb;
        }
    }
}

// ---------------------------------------------------------------------------
// Fused QK-GEMM + attention. One CTA per (b,h), 512 threads.
// Phase 0: 1-term QK (W hi, x hi), K chunks of 64, stage = Ah|Bh (ROWB 144).
// ---------------------------------------------------------------------------
#define QK_ROWB 144
#define QK_SEG  18432
#define STAGE_QK (2*QK_SEG)    // 36864
// stages occupy [0, 110592)

#define AQK_ROWB 272
#define AA_ROWB  272
#define AV_ROWB  272
#define AE_STRIDE 132
#define AST_STRIDE 132
#define AOFF_Q   0
#define AOFF_K   34816
#define AOFF_A   0
#define AOFF_E   110592
#define AOFF_ST  110592
#define AOFF_V   180224
#define AV_BUFB  17408         // 64 rows * 272
#define ATT_SMEM 215040

__device__ __forceinline__ void load_chunk_qk(uint32_t sb, int tid, int k0, size_t bofs)
{
    const __half* srcs[2] = { g_w_hi + k0, g_xt_hi + bofs + k0 };
    #pragma unroll
    for (int i = tid; i < 2048; i += 512) {
        int seg = i >> 10;
        int r = (i & 1023) >> 3, u = i & 7;
        cp16(sb + seg*QK_SEG + r*QK_ROWB + u*16, srcs[seg] + (size_t)r*Cc + u*8);
    }
    CP_COMMIT();
}

__device__ __forceinline__ void att_load_v(uint32_t sbv, int tid, int b, int h, int cc)
{
    const __half* src0 = g_v16 + (((size_t)b*Cc + cc)*Hh + h)*Ww;
    #pragma unroll
    for (int i = tid; i < 1024; i += 512) {
        int r = i >> 4, u = i & 15;
        cp16(sbv + r*AV_ROWB + u*16, src0 + (size_t)r*HW + u*8);
    }
    CP_COMMIT();
}

__global__ void __launch_bounds__(512, 1) attn_kernel(
    const float* __restrict__ x,
    const float* __restrict__ gamma_p,
    float* __restrict__ outp)
{
    extern __shared__ char smem[];
    const uint32_t sbase = smem_u32(smem);
    const int tid = threadIdx.x, wid = tid >> 5, lane = tid & 31;
    const int g = lane >> 2, q = lane & 3;
    const int bh = blockIdx.x;
    const int b = bh >> 7, h = bh & 127;
    const float gma = gamma_p[0];
    const size_t bofs = ((size_t)b*HW + h*128)*Cc;
    const int lmat = lane >> 3, lrow = lane & 7;

    att_load_v(sbase + AOFF_V, tid, b, h, 0);
    att_load_v(sbase + AOFF_V + AV_BUFB, tid, b, h, 64);

    // ======================= Phase 0: QK GEMM (1-term, k64) ================
    {
        const int wm = wid & 3, wn = wid >> 2;   // warp tile 32m x 32n
        float acc[2][4][4];
        #pragma unroll
        for (int i = 0; i < 2; i++)
            #pragma unroll
            for (int j = 0; j < 4; j++)
                #pragma unroll
                for (int e = 0; e < 4; e++) acc[i][j][e] = 0.f;

        load_chunk_qk(sbase, tid, 0, bofs);
        load_chunk_qk(sbase + STAGE_QK, tid, 64, bofs);

        for (int c = 0; c < 8; c++) {
            if (c < 7) { CP_WAIT_GROUP(1); } else { CP_WAIT_GROUP(0); }
            __syncthreads();
            if (c + 2 < 8)
                load_chunk_qk(sbase + ((c+2) % 3)*STAGE_QK, tid, (c+2)*64, bofs);

            const uint32_t sb = sbase + (c % 3)*STAGE_QK;
            #pragma unroll
            for (int ks = 0; ks < 4; ks++) {
                uint32_t ah[2][4], bhf[4][2];
                #pragma unroll
                for (int tm = 0; tm < 2; tm++) {
                    uint32_t ra = sb + (wm*32 + tm*16 + (lmat&1)*8 + lrow)*QK_ROWB + ks*32 + (lmat>>1)*16;
                    ldsm4(ah[tm][0], ah[tm][1], ah[tm][2], ah[tm][3], ra);
                }
                #pragma unroll
                for (int tp = 0; tp < 2; tp++) {
                    uint32_t rb = sb + QK_SEG + (wn*32 + (tp*2 + (lmat>>1))*8 + lrow)*QK_ROWB + ks*32 + (lmat&1)*16;
                    ldsm4(bhf[tp*2][0], bhf[tp*2][1], bhf[tp*2+1][0], bhf[tp*2+1][1], rb);
                }
                #pragma unroll
                for (int tm = 0; tm < 2; tm++)
                    #pragma unroll
                    for (int tn = 0; tn < 4; tn++)
                        mma_f16(acc[tm][tn], ah[tm][0], ah[tm][1], ah[tm][2], ah[tm][3], bhf[tn][0], bhf[tn][1]);
            }
        }
        __syncthreads();   // all stage reads done before sq/sk overlay

        // Epilogue: bias, pack (hi,lo) into smem sq/sk (overlays stages).
        #pragma unroll
        for (int tm = 0; tm < 2; tm++) {
            int mrow = wm*32 + tm*16 + g;
            float bias0 = g_bias[mrow];
            float bias1 = g_bias[mrow + 8];
            #pragma unroll
            for (int tn = 0; tn < 4; tn++) {
                int w = wn*32 + tn*8 + q*2;
                uint32_t p0 = pack_hilo(acc[tm][tn][0] + bias0);
                uint32_t p1 = pack_hilo(acc[tm][tn][1] + bias0);
                uint32_t p2 = pack_hilo(acc[tm][tn][2] + bias1);
                uint32_t p3 = pack_hilo(acc[tm][tn][3] + bias1);
                #pragma unroll
                for (int rr = 0; rr < 2; rr++) {
                    int oc = mrow + rr*8;
                    uint32_t pa = rr ? p2 : p0;
                    uint32_t pb = rr ? p3 : p1;
                    if (oc < 64) {
                        int i = oc*2 + (w >> 6), cc = w & 63;
                        *(uint2*)(smem + AOFF_Q + i*AQK_ROWB + cc*4) = make_uint2(pa, pb);
                    } else {
                        int cq = oc - 64, cc = w >> 1;
                        *(uint32_t*)(smem + AOFF_K + cq*AQK_ROWB + cc*4)        = pa;
                        *(uint32_t*)(smem + AOFF_K + (64 + cq)*AQK_ROWB + cc*4) = pb;
                    }
                }
            }
        }
    }
    __syncthreads();

    const int wi = wid & 3;
    const int wj = wid >> 2;

    // ======================= Phase 1: energy (3-term) ======================
    {
        float e[2][4][4];
        #pragma unroll
        for (int a1 = 0; a1 < 2; a1++)
            #pragma unroll
            for (int a2 = 0; a2 < 4; a2++)
                #pragma unroll
                for (int a3 = 0; a3 < 4; a3++) e[a1][a2][a3] = 0.f;

        #pragma unroll
        for (int ks = 0; ks < 4; ks++) {
            uint32_t ah[2][4], al[2][4], bh_[4][2], bl_[4][2];
            #pragma unroll
            for (int ti = 0; ti < 2; ti++) {
                uint32_t ra = AOFF_Q + (wi*32 + ti*16 + g)*AQK_ROWB + ks*64 + q*8;
                uint2 w00 = *(const uint2*)(smem + ra);
                uint2 w10 = *(const uint2*)(smem + ra + 8*AQK_ROWB);
                uint2 w01 = *(const uint2*)(smem + ra + 32);
                uint2 w11 = *(const uint2*)(smem + ra + 8*AQK_ROWB + 32);
                ah[ti][0] = prmt(w00.x, w00.y, 0x5410); al[ti][0] = prmt(w00.x, w00.y, 0x7632);
                ah[ti][1] = prmt(w10.x, w10.y, 0x5410); al[ti][1] = prmt(w10.x, w10.y, 0x7632);
                ah[ti][2] = prmt(w01.x, w01.y, 0x5410); al[ti][2] = prmt(w01.x, w01.y, 0x7632);
                ah[ti][3] = prmt(w11.x, w11.y, 0x5410); al[ti][3] = prmt(w11.x, w11.y, 0x7632);
            }
            #pragma unroll
            for (int tn = 0; tn < 4; tn++) {
                uint32_t rb = AOFF_K + (wj*32 + tn*8 + g)*AQK_ROWB + ks*64 + q*8;
                uint2 u0 = *(const uint2*)(smem + rb);
                uint2 u1 = *(const uint2*)(smem + rb + 32);
                bh_[tn][0] = prmt(u0.x, u0.y, 0x5410); bl_[tn][0] = prmt(u0.x, u0.y, 0x7632);
                bh_[tn][1] = prmt(u1.x, u1.y, 0x5410); bl_[tn][1] = prmt(u1.x, u1.y, 0x7632);
            }
            #pragma unroll
            for (int ti = 0; ti < 2; ti++)
                #pragma unroll
                for (int tn = 0; tn < 4; tn++) {
                    mma_f16(e[ti][tn], ah[ti][0], ah[ti][1], ah[ti][2], ah[ti][3], bh_[tn][0], bh_[tn][1]);
                    mma_f16(e[ti][tn], al[ti][0], al[ti][1], al[ti][2], al[ti][3], bh_[tn][0], bh_[tn][1]);
                    mma_f16(e[ti][tn], ah[ti][0], ah[ti][1], ah[ti][2], ah[ti][3], bl_[tn][0], bl_[tn][1]);
                }
        }
        float* Ef = (float*)(smem + AOFF_E);
        #pragma unroll
        for (int ti = 0; ti < 2; ti++)
            #pragma unroll
            for (int tn = 0; tn < 4; tn++) {
                int ri = wi*32 + ti*16 + g, cj = wj*32 + tn*8 + 2*q;
                *(float2*)&Ef[ri*AE_STRIDE + cj]     = make_float2(e[ti][tn][0], e[ti][tn][1]);
                *(float2*)&Ef[(ri+8)*AE_STRIDE + cj] = make_float2(e[ti][tn][2], e[ti][tn][3]);
            }
    }
    __syncthreads();

    // ======================= Phase 2: softmax + pack A =====================
    {
        float* Ef = (float*)(smem + AOFF_E);
        int i = tid >> 2, qt = tid & 3;
        float* row = Ef + i*AE_STRIDE + qt*32;
        float mx = -1e30f;
        #pragma unroll 8
        for (int j = 0; j < 32; j++) mx = fmaxf(mx, row[j]);
        mx = fmaxf(mx, __shfl_xor_sync(0xFFFFFFFFu, mx, 1));
        mx = fmaxf(mx, __shfl_xor_sync(0xFFFFFFFFu, mx, 2));
        float s = 0.f;
        #pragma unroll 8
        for (int j = 0; j < 32; j++) { float p = __expf(row[j] - mx); row[j] = p; s += p; }
        s += __shfl_xor_sync(0xFFFFFFFFu, s, 1);
        s += __shfl_xor_sync(0xFFFFFFFFu, s, 2);
        float inv = 1.f / s;
        uint32_t* arow = (uint32_t*)(smem + AOFF_A + i*AA_ROWB + qt*64);
        #pragma unroll 8
        for (int j = 0; j < 32; j += 2)
            arow[j >> 1] = pack2h(row[j]*inv, row[j+1]*inv);
    }
    __syncthreads();

    // ======================= Phase 3: out = A @ V (8 chunks of 64 ch) ======
    float* STf = (float*)(smem + AOFF_ST);
    for (int ci = 0; ci < 8; ci++) {
        if (ci < 7) { CP_WAIT_GROUP(1); } else { CP_WAIT_GROUP(0); }
        __syncthreads();

        const uint32_t vb = AOFF_V + (ci & 1)*AV_BUFB;
        float o[2][2][4];
        #pragma unroll
        for (int a1 = 0; a1 < 2; a1++)
            #pragma unroll
            for (int a2 = 0; a2 < 2; a2++)
                #pragma unroll
                for (int a3 = 0; a3 < 4; a3++) o[a1][a2][a3] = 0.f;

        #pragma unroll
        for (int ks = 0; ks < 8; ks++) {
            uint32_t a0[2], a1r[2], a2[2], a3[2], b0[2], b1[2];
            #pragma unroll
            for (int ti = 0; ti < 2; ti++) {
                uint32_t ra = AOFF_A + (wi*32 + ti*16 + g)*AA_ROWB + ks*32 + q*4;
                a0[ti]  = *(const uint32_t*)(smem + ra);
                a1r[ti] = *(const uint32_t*)(smem + ra + 8*AA_ROWB);
                a2[ti]  = *(const uint32_t*)(smem + ra + 16);
                a3[ti]  = *(const uint32_t*)(smem + ra + 8*AA_ROWB + 16);
            }
            #pragma unroll
            for (int tn = 0; tn < 2; tn++) {
                uint32_t rb = vb + (wj*16 + tn*8 + g)*AV_ROWB + ks*32 + q*4;
                b0[tn] = *(const uint32_t*)(smem + rb);
                b1[tn] = *(const uint32_t*)(smem + rb + 16);
            }
            #pragma unroll
            for (int ti = 0; ti < 2; ti++)
                #pragma unroll
                for (int tn = 0; tn < 2; tn++)
                    mma_f16(o[ti][tn], a0[ti], a1r[ti], a2[ti], a3[ti], b0[tn], b1[tn]);
        }

        #pragma unroll
        for (int ti = 0; ti < 2; ti++)
            #pragma unroll
            for (int tn = 0; tn < 2; tn++) {
                int ri = wi*32 + ti*16 + g, cj = wj*16 + tn*8 + 2*q;
                STf[cj*AST_STRIDE + ri]          = o[ti][tn][0];
                STf[(cj+1)*AST_STRIDE + ri]      = o[ti][tn][1];
                STf[cj*AST_STRIDE + ri + 8]      = o[ti][tn][2];
                STf[(cj+1)*AST_STRIDE + ri + 8]  = o[ti][tn][3];
            }
        __syncthreads();

        if (ci + 2 < 8) att_load_v(sbase + vb, tid, b, h, (ci+2)*64);

        #pragma unroll
        for (int rr = 0; rr < 4; rr++) {
            int r = wid*4 + rr;
            int c = ci*64 + r;
            size_t gofs = (((size_t)b*Cc + c)*Hh + h)*Ww + lane*4;
            float4 xr = *(const float4*)(x + gofs);
            float4 ov = *(const float4*)(STf + r*AST_STRIDE + lane*4);
            *(float4*)(outp + gofs) = make_float4(gma*ov.x + xr.x, gma*ov.y + xr.y,
                                                  gma*ov.z + xr.z, gma*ov.w + xr.w);
        }
    }
}

// ---------------------------------------------------------------------------
extern "C" void kernel_launch(void* const* d_in, const int* in_sizes, int n_in,
                              void* d_out, int out_size)
{
    (void)in_sizes; (void)n_in; (void)out_size;
    const float* x     = (const float*)d_in[0];
    const float* Wq    = (const float*)d_in[1];
    const float* bq    = (const float*)d_in[2];
    const float* Wk    = (const float*)d_in[3];
    const float* bk    = (const float*)d_in[4];
    const float* Wv    = (const float*)d_in[5];
    const float* bv    = (const float*)d_in[6];
    const float* gamma = (const float*)d_in[7];
    float* out = (float*)d_out;

    dim3 gx(HW/64, Cc/64, Bn);
    prep_all<<<gx, 256>>>(x, Wq, bq, Wk, bk, Wv, bv);

    cudaFuncSetAttribute(qkv_gemm_v, cudaFuncAttributeMaxDynamicSharedMemorySize, SM_V);
    qkv_gemm_v<<<dim3(4, 128, Bn), 256, SM_V>>>();

    cudaFuncSetAttribute(attn_kernel, cudaFuncAttributeMaxDynamicSharedMemorySize, ATT_SMEM);
    attn_kernel<<<Bn*Hh, 512, ATT_SMEM>>>(x, gamma, out);
}